// round 11
// baseline (speedup 1.0000x reference)
#include <cuda_runtime.h>
#include <cuda_bf16.h>
#include <cuda_fp16.h>
#include <math.h>
#include <stdint.h>

// ---------------- problem constants ----------------
#define NN     50000
#define FIN    256
#define HIDDIM 128
#define NHEADS 8
#define HDIM   16
#define NCLS   64
#define NEDGE  1250000
#define NBF    44
#define EPSV   1e-4f
#define ALPHAV 0.1f

#define NTILES ((NN + 31) / 32)

// ---------------- scratch (device globals; no runtime alloc) ----------------
__device__ float g_bias1[512];
__device__ __nv_bfloat16 g_Bt_hi[512 * 256];
__device__ __nv_bfloat16 g_Bt_lo[512 * 256];
__device__ __nv_bfloat16 g_B2_hi[64 * 256];
__device__ __nv_bfloat16 g_B2_lo[64 * 256];
__device__ __nv_bfloat16 g_A_hi[(size_t)NN * 256];
__device__ __nv_bfloat16 g_A_lo[(size_t)NN * 256];
__device__ float g_C1[(size_t)NN * 512];
__device__ float g_kmax[NHEADS];
__device__ float g_kcum[NHEADS * NBF];
__device__ float g_ctx[NHEADS * HDIM * NBF];   // [h][d][m]
__device__ __nv_bfloat16 g_h_hi[(size_t)NN * 256];
__device__ __nv_bfloat16 g_h_lo[(size_t)NN * 256];
__device__ float  g_x0[(size_t)NN * NCLS];
__device__ __half g_x0h[(size_t)NN * NCLS];
__device__ __half g_ha[(size_t)NN * NCLS];
__device__ __half g_hb[(size_t)NN * NCLS];
__device__ int   g_cnt[NN];
__device__ int   g_off[NN + 1];
__device__ int   g_cursor[NN];
__device__ float g_dis[NN];
__device__ int2  g_csr[NEDGE];

// ---------------- PTX helpers ----------------
__device__ __forceinline__ uint32_t smem_u32(const void* p) {
    uint32_t a;
    asm("{ .reg .u64 t; cvta.to.shared.u64 t, %1; cvt.u32.u64 %0, t; }" : "=r"(a) : "l"(p));
    return a;
}
#define LDMX4(r0, r1, r2, r3, addr)                                          \
    asm volatile("ldmatrix.sync.aligned.m8n8.x4.shared.b16 {%0,%1,%2,%3}, [%4];" \
                 : "=r"(r0), "=r"(r1), "=r"(r2), "=r"(r3) : "r"(addr))
#define MMA16816(c, a, b0v, b1v)                                             \
    asm volatile("mma.sync.aligned.m16n8k16.row.col.f32.bf16.bf16.f32 "      \
                 "{%0,%1,%2,%3},{%4,%5,%6,%7},{%8,%9},{%0,%1,%2,%3};"        \
                 : "+f"((c)[0]), "+f"((c)[1]), "+f"((c)[2]), "+f"((c)[3])    \
                 : "r"((a)[0]), "r"((a)[1]), "r"((a)[2]), "r"((a)[3]),       \
                   "r"(b0v), "r"(b1v))
__device__ __forceinline__ void cp_async16(uint32_t saddr, const void* gaddr, uint32_t srcsize) {
    asm volatile("cp.async.cg.shared.global [%0], [%1], 16, %2;"
                 :: "r"(saddr), "l"(gaddr), "r"(srcsize) : "memory");
}
#define CP_COMMIT() asm volatile("cp.async.commit_group;" ::: "memory")
#define CP_WAIT0()  asm volatile("cp.async.wait_group 0;" ::: "memory")

// ---------------- misc helpers ----------------
__device__ __forceinline__ void atomicMaxFloat(float* addr, float val) {
    int* ia = (int*)addr;
    int old = *ia;
    while (__int_as_float(old) < val) {
        int assumed = old;
        old = atomicCAS(ia, assumed, __float_as_int(val));
        if (old == assumed) break;
    }
}

__device__ __forceinline__ float fexp(float x) {
    float y = fmaxf(x * 1.44269504f, -125.0f);
    float z = y + 12582912.0f;
    int   n = __float_as_int(z) - 0x4B400000;
    float f = y - (z - 12582912.0f);
    float q = 0.00133335581f;
    q = q * f + 0.00961812911f;
    q = q * f + 0.0555041087f;
    q = q * f + 0.240226507f;
    q = q * f + 0.693147181f;
    q = q * f + 1.0f;
    return q * __int_as_float((n + 127) << 23);
}

// ---------------- prep: pack weights + split data + init (fused) ----------------
__global__ __launch_bounds__(256) void prep_kernel(
    const float* __restrict__ data,
    const float* __restrict__ qw, const float* __restrict__ kw,
    const float* __restrict__ vw, const float* __restrict__ l1w,
    const float* __restrict__ qb, const float* __restrict__ kb,
    const float* __restrict__ vb, const float* __restrict__ l1b,
    const float* __restrict__ l2w) {
    int gt = blockIdx.x * 256 + threadIdx.x;
    int NT = gridDim.x * 256;
    if (gt < NHEADS) g_kmax[gt] = -3e38f;
    for (int i = gt; i < NHEADS * NBF; i += NT) g_kcum[i] = 0.f;
    for (int i = gt; i < NHEADS * HDIM * NBF; i += NT) g_ctx[i] = 0.f;
    for (int i = gt; i < NN; i += NT) g_cnt[i] = 0;
    for (int i = gt; i < 512 * 256; i += NT) {
        int n = i >> 8, k = i & 255;
        const float* src = (n < 128) ? qw : (n < 256) ? kw : (n < 384) ? vw : l1w;
        float w = src[k * 128 + (n & 127)];
        __nv_bfloat16 hi = __float2bfloat16(w);
        g_Bt_hi[i] = hi;
        g_Bt_lo[i] = __float2bfloat16(w - __bfloat162float(hi));
    }
    if (gt < 512) {
        const float* sb = (gt < 128) ? qb : (gt < 256) ? kb : (gt < 384) ? vb : l1b;
        g_bias1[gt] = sb[gt & 127];
    }
    for (int i = gt; i < 64 * 256; i += NT) {
        int n = i >> 8, k = i & 255;
        float w = l2w[k * 64 + n];
        __nv_bfloat16 hi = __float2bfloat16(w);
        g_B2_hi[i] = hi;
        g_B2_lo[i] = __float2bfloat16(w - __bfloat162float(hi));
    }
    for (int i4 = gt; i4 < NN * 64; i4 += NT) {
        size_t base = (size_t)i4 * 4;
        float4 v = *(const float4*)&data[base];
        __nv_bfloat16 h0 = __float2bfloat16(v.x), h1 = __float2bfloat16(v.y);
        __nv_bfloat16 h2 = __float2bfloat16(v.z), h3 = __float2bfloat16(v.w);
        __nv_bfloat162* ph = (__nv_bfloat162*)&g_A_hi[base];
        ph[0] = __nv_bfloat162(h0, h1);
        ph[1] = __nv_bfloat162(h2, h3);
        __nv_bfloat162* pl = (__nv_bfloat162*)&g_A_lo[base];
        pl[0] = __nv_bfloat162(__float2bfloat16(v.x - __bfloat162float(h0)),
                               __float2bfloat16(v.y - __bfloat162float(h1)));
        pl[1] = __nv_bfloat162(__float2bfloat16(v.z - __bfloat162float(h2)),
                               __float2bfloat16(v.w - __bfloat162float(h3)));
    }
}

// ---------------- HMMA split-bf16 GEMM1 ----------------
#define HG_SMEM 65536
__global__ __launch_bounds__(256) void hmma_gemm_kernel() {
    extern __shared__ char smem[];
    const uint32_t sb = smem_u32(smem);
    const int t = threadIdx.x;
    const int w = t >> 5;
    const int lane = t & 31;
    const int wm = w >> 1, wn = w & 1;
    const int bm = blockIdx.x * 128;
    const int bn = blockIdx.y * 128;
    const uint32_t AH = 0, AL = 16384, BH = 32768, BL = 49152;

    float acc[2][8][4];
#pragma unroll
    for (int i = 0; i < 2; i++)
#pragma unroll
        for (int j = 0; j < 8; j++)
#pragma unroll
            for (int k = 0; k < 4; k++) acc[i][j][k] = 0.f;

    const int srow = t >> 3;
    const int schk = t & 7;

    for (int c = 0; c < 4; c++) {
        const int k0 = c * 64;
        if (c) __syncthreads();
#pragma unroll
        for (int rep = 0; rep < 4; rep++) {
            int row = rep * 32 + srow;
            uint32_t so = (uint32_t)(row * 128 + ((schk ^ (row & 7)) << 4));
            bool in = (bm + row) < NN;
            uint32_t asz = in ? 16u : 0u;
            size_t ga = (size_t)(in ? (bm + row) : 0) * 256 + k0 + schk * 8;
            cp_async16(sb + AH + so, &g_A_hi[ga], asz);
            cp_async16(sb + AL + so, &g_A_lo[ga], asz);
            size_t gb = (size_t)(bn + row) * 256 + k0 + schk * 8;
            cp_async16(sb + BH + so, &g_Bt_hi[gb], 16u);
            cp_async16(sb + BL + so, &g_Bt_lo[gb], 16u);
        }
        CP_COMMIT();
        CP_WAIT0();
        __syncthreads();

#pragma unroll
        for (int ks = 0; ks < 4; ks++) {
            uint32_t ah[2][4], al[2][4], bh[4][4], bl[4][4];
            int lr = lane & 15;
            int kh = lane >> 4;
            int chunk = ks * 2 + kh;
#pragma unroll
            for (int im = 0; im < 2; im++) {
                int row = wm * 32 + im * 16 + lr;
                uint32_t so = (uint32_t)(row * 128 + ((chunk ^ (row & 7)) << 4));
                LDMX4(ah[im][0], ah[im][1], ah[im][2], ah[im][3], sb + AH + so);
                LDMX4(al[im][0], al[im][1], al[im][2], al[im][3], sb + AL + so);
            }
#pragma unroll
            for (int in = 0; in < 4; in++) {
                int row = wn * 64 + in * 16 + lr;
                uint32_t so = (uint32_t)(row * 128 + ((chunk ^ (row & 7)) << 4));
                LDMX4(bh[in][0], bh[in][1], bh[in][2], bh[in][3], sb + BH + so);
                LDMX4(bl[in][0], bl[in][1], bl[in][2], bl[in][3], sb + BL + so);
            }
#pragma unroll
            for (int im = 0; im < 2; im++) {
#pragma unroll
                for (int in = 0; in < 4; in++) {
                    MMA16816(acc[im][2 * in],     ah[im], bh[in][0], bh[in][2]);
                    MMA16816(acc[im][2 * in + 1], ah[im], bh[in][1], bh[in][3]);
                    MMA16816(acc[im][2 * in],     ah[im], bl[in][0], bl[in][2]);
                    MMA16816(acc[im][2 * in + 1], ah[im], bl[in][1], bl[in][3]);
                    MMA16816(acc[im][2 * in],     al[im], bh[in][0], bh[in][2]);
                    MMA16816(acc[im][2 * in + 1], al[im], bh[in][1], bh[in][3]);
                }
            }
        }
    }
    int gid = lane >> 2, tig = lane & 3;
#pragma unroll
    for (int im = 0; im < 2; im++) {
        int m0 = bm + wm * 32 + im * 16 + gid;
#pragma unroll
        for (int s = 0; s < 8; s++) {
            int n = bn + wn * 64 + s * 8 + tig * 2;
            float b0 = g_bias1[n], b1 = g_bias1[n + 1];
            if (m0 < NN) {
                float2 v = make_float2(acc[im][s][0] + b0, acc[im][s][1] + b1);
                *(float2*)&g_C1[(size_t)m0 * 512 + n] = v;
            }
            if (m0 + 8 < NN) {
                float2 v = make_float2(acc[im][s][2] + b0, acc[im][s][3] + b1);
                *(float2*)&g_C1[(size_t)(m0 + 8) * 512 + n] = v;
            }
        }
    }
}

// ---------------- HMMA split-bf16 GEMM2 ----------------
#define G2_SMEM (16384 * 2 + 16384)
__global__ __launch_bounds__(256) void gemm2_kernel(const float* __restrict__ bext) {
    extern __shared__ char smem[];
    const uint32_t sb = smem_u32(smem);
    const int t = threadIdx.x;
    const int w = t >> 5;
    const int lane = t & 31;
    const int wm = w >> 1, wn = w & 1;
    const int bm = blockIdx.x * 128;
    const uint32_t AH = 0, AL = 16384, BH = 32768, BL = 40960;

    float acc[2][4][4];
#pragma unroll
    for (int i = 0; i < 2; i++)
#pragma unroll
        for (int j = 0; j < 4; j++)
#pragma unroll
            for (int k = 0; k < 4; k++) acc[i][j][k] = 0.f;

    const int srow = t >> 3;
    const int schk = t & 7;

    for (int c = 0; c < 4; c++) {
        const int k0 = c * 64;
        if (c) __syncthreads();
#pragma unroll
        for (int rep = 0; rep < 4; rep++) {
            int row = rep * 32 + srow;
            uint32_t so = (uint32_t)(row * 128 + ((schk ^ (row & 7)) << 4));
            bool in = (bm + row) < NN;
            uint32_t asz = in ? 16u : 0u;
            size_t ga = (size_t)(in ? (bm + row) : 0) * 256 + k0 + schk * 8;
            cp_async16(sb + AH + so, &g_h_hi[ga], asz);
            cp_async16(sb + AL + so, &g_h_lo[ga], asz);
        }
#pragma unroll
        for (int rep = 0; rep < 2; rep++) {
            int row = rep * 32 + srow;
            uint32_t so = (uint32_t)(row * 128 + ((schk ^ (row & 7)) << 4));
            size_t gb = (size_t)row * 256 + k0 + schk * 8;
            cp_async16(sb + BH + so, &g_B2_hi[gb], 16u);
            cp_async16(sb + BL + so, &g_B2_lo[gb], 16u);
        }
        CP_COMMIT();
        CP_WAIT0();
        __syncthreads();
#pragma unroll
        for (int ks = 0; ks < 4; ks++) {
            uint32_t ah[2][4], al[2][4], bh[2][4], bl[2][4];
            int lr = lane & 15;
            int kh = lane >> 4;
            int chunk = ks * 2 + kh;
#pragma unroll
            for (int im = 0; im < 2; im++) {
                int row = wm * 32 + im * 16 + lr;
                uint32_t so = (uint32_t)(row * 128 + ((chunk ^ (row & 7)) << 4));
                LDMX4(ah[im][0], ah[im][1], ah[im][2], ah[im][3], sb + AH + so);
                LDMX4(al[im][0], al[im][1], al[im][2], al[im][3], sb + AL + so);
            }
#pragma unroll
            for (int in = 0; in < 2; in++) {
                int row = wn * 32 + in * 16 + lr;
                uint32_t so = (uint32_t)(row * 128 + ((chunk ^ (row & 7)) << 4));
                LDMX4(bh[in][0], bh[in][1], bh[in][2], bh[in][3], sb + BH + so);
                LDMX4(bl[in][0], bl[in][1], bl[in][2], bl[in][3], sb + BL + so);
            }
#pragma unroll
            for (int im = 0; im < 2; im++) {
#pragma unroll
                for (int in = 0; in < 2; in++) {
                    MMA16816(acc[im][2 * in],     ah[im], bh[in][0], bh[in][2]);
                    MMA16816(acc[im][2 * in + 1], ah[im], bh[in][1], bh[in][3]);
                    MMA16816(acc[im][2 * in],     ah[im], bl[in][0], bl[in][2]);
                    MMA16816(acc[im][2 * in + 1], ah[im], bl[in][1], bl[in][3]);
                    MMA16816(acc[im][2 * in],     al[im], bh[in][0], bh[in][2]);
                    MMA16816(acc[im][2 * in + 1], al[im], bh[in][1], bh[in][3]);
                }
            }
        }
    }
    int gid = lane >> 2, tig = lane & 3;
#pragma unroll
    for (int im = 0; im < 2; im++) {
        int m0 = bm + wm * 32 + im * 16 + gid;
#pragma unroll
        for (int s = 0; s < 4; s++) {
            int n = wn * 32 + s * 8 + tig * 2;
            float b0 = bext[n], b1 = bext[n + 1];
            if (m0 < NN) {
                float x = acc[im][s][0] + b0, y = acc[im][s][1] + b1;
                x = x > 0.f ? x : expm1f(x);
                y = y > 0.f ? y : expm1f(y);
                *(float2*)&g_x0[(size_t)m0 * 64 + n] = make_float2(x, y);
                *(__half2*)&g_x0h[(size_t)m0 * 64 + n] = __floats2half2_rn(x, y);
            }
            if (m0 + 8 < NN) {
                float x = acc[im][s][2] + b0, y = acc[im][s][3] + b1;
                x = x > 0.f ? x : expm1f(x);
                y = y > 0.f ? y : expm1f(y);
                *(float2*)&g_x0[(size_t)(m0 + 8) * 64 + n] = make_float2(x, y);
                *(__half2*)&g_x0h[(size_t)(m0 + 8) * 64 + n] = __floats2half2_rn(x, y);
            }
        }
    }
}

// ---------------- performer: kmax (row-major tile, LDS.128) ----------------
__global__ __launch_bounds__(256) void kmax_kernel(const float* __restrict__ proj) {
    __shared__ float ks[32][132];
    __shared__ float proj_s[NBF * HDIM];
    int t = threadIdx.x;
    int row0 = blockIdx.x * 32;
    for (int i = t; i < NBF * HDIM; i += 256) proj_s[i] = proj[i];
    for (int i = t; i < 32 * 32; i += 256) {
        int r = i >> 5, c4 = i & 31;
        float4 v = make_float4(0.f, 0.f, 0.f, 0.f);
        if (row0 + r < NN) v = *(const float4*)&g_C1[(size_t)(row0 + r) * 512 + 128 + c4 * 4];
        *(float4*)&ks[r][c4 * 4] = v;
    }
    __syncthreads();
    int h = t >> 5, r = t & 31;
    float mx = -3e38f;
    if (row0 + r < NN) {
        float k[HDIM];
#pragma unroll
        for (int d4 = 0; d4 < 4; d4++) {
            float4 v = *(const float4*)&ks[r][h * 16 + d4 * 4];
            k[d4 * 4] = v.x * 0.5f; k[d4 * 4 + 1] = v.y * 0.5f;
            k[d4 * 4 + 2] = v.z * 0.5f; k[d4 * 4 + 3] = v.w * 0.5f;
        }
#pragma unroll
        for (int m = 0; m < NBF; m++) {
            float s = 0.f;
#pragma unroll
            for (int d4 = 0; d4 < 4; d4++) {
                float4 p = *(const float4*)&proj_s[m * 16 + d4 * 4];
                s += k[d4 * 4] * p.x + k[d4 * 4 + 1] * p.y + k[d4 * 4 + 2] * p.z + k[d4 * 4 + 3] * p.w;
            }
            mx = fmaxf(mx, s);
        }
    }
#pragma unroll
    for (int o = 16; o > 0; o >>= 1) mx = fmaxf(mx, __shfl_xor_sync(0xffffffffu, mx, o));
    if (r == 0) atomicMaxFloat(&g_kmax[h], mx);
}

// ---------------- performer: kp (row-major tile, hoisted diag, LDS.128) ----------
#define KPB 444
__global__ __launch_bounds__(352) void kp_acc_kernel(const float* __restrict__ proj) {
    __shared__ float s[32][264];
    __shared__ float diag_s[32][8];
    int t = threadIdx.x;
    int h = t / NBF, m = t - h * NBF;
    float pm[HDIM];
#pragma unroll
    for (int d = 0; d < HDIM; d++) pm[d] = proj[m * HDIM + d];
    float kmaxh = g_kmax[h];
    const float ratio = rsqrtf((float)NBF);
    float ctx[HDIM];
    float kc = 0.f;
#pragma unroll
    for (int d = 0; d < HDIM; d++) ctx[d] = 0.f;

    for (int tile = blockIdx.x; tile < NTILES; tile += gridDim.x) {
        int row0 = tile * 32;
        __syncthreads();
        for (int i = t; i < 32 * 64; i += 352) {
            int r = i >> 6, c4 = i & 63;
            float4 v = make_float4(0.f, 0.f, 0.f, 0.f);
            if (row0 + r < NN) v = *(const float4*)&g_C1[(size_t)(row0 + r) * 512 + 128 + c4 * 4];
            *(float4*)&s[r][c4 * 4] = v;
        }
        __syncthreads();
        if (t < 256) {
            int rr = t >> 3, hh = t & 7;
            float sum = 0.f;
#pragma unroll
            for (int d4 = 0; d4 < 4; d4++) {
                float4 v = *(const float4*)&s[rr][hh * 16 + d4 * 4];
                sum += v.x * v.x + v.y * v.y + v.z * v.z + v.w * v.w;
            }
            diag_s[rr][hh] = 0.125f * sum;
        }
        __syncthreads();
        int rmax = min(32, NN - row0);
        for (int r = 0; r < rmax; r++) {
            float draw = 0.f;
#pragma unroll
            for (int d4 = 0; d4 < 4; d4++) {
                float4 v = *(const float4*)&s[r][h * 16 + d4 * 4];
                draw += v.x * pm[d4 * 4] + v.y * pm[d4 * 4 + 1] + v.z * pm[d4 * 4 + 2] + v.w * pm[d4 * 4 + 3];
            }
            float kpv = ratio * (fexp(0.5f * draw - diag_s[r][h] - kmaxh) + EPSV);
            kc += kpv;
#pragma unroll
            for (int d4 = 0; d4 < 4; d4++) {
                float4 v = *(const float4*)&s[r][128 + h * 16 + d4 * 4];
                ctx[d4 * 4] += kpv * v.x; ctx[d4 * 4 + 1] += kpv * v.y;
                ctx[d4 * 4 + 2] += kpv * v.z; ctx[d4 * 4 + 3] += kpv * v.w;
            }
        }
    }
    atomicAdd(&g_kcum[h * NBF + m], kc);
#pragma unroll
    for (int d = 0; d < HDIM; d++) atomicAdd(&g_ctx[(h * HDIM + d) * NBF + m], ctx[d]);
}

// ---------------- attention (row-major q tile, ctx [h][m][d], LDS.128) -----------
__global__ __launch_bounds__(256) void attn_kernel(const float* __restrict__ proj) {
    __shared__ float qs[32][132];
    __shared__ float proj_s[NBF * HDIM];
    __shared__ float kcum_s[NHEADS * NBF];
    __shared__ float ctxr[NHEADS][NBF * HDIM];
    int t = threadIdx.x;
    int row0 = blockIdx.x * 32;
    for (int i = t; i < NBF * HDIM; i += 256) proj_s[i] = proj[i];
    for (int i = t; i < NHEADS * NBF; i += 256) kcum_s[i] = g_kcum[i];
    for (int i = t; i < NHEADS * NBF * HDIM; i += 256) {
        int hh = i / (NBF * HDIM);
        int rem = i - hh * NBF * HDIM;
        int mm = rem >> 4, dd = rem & 15;
        ctxr[hh][mm * 16 + dd] = g_ctx[(hh * HDIM + dd) * NBF + mm];
    }
    for (int i = t; i < 32 * 32; i += 256) {
        int r = i >> 5, c4 = i & 31;
        float4 v = make_float4(0.f, 0.f, 0.f, 0.f);
        if (row0 + r < NN) v = *(const float4*)&g_C1[(size_t)(row0 + r) * 512 + c4 * 4];
        *(float4*)&qs[r][c4 * 4] = v;
    }
    for (int i = t; i < 32 * 64; i += 256) {
        int r = i >> 6, dp = (i & 63) * 2;
        if (row0 + r < NN) {
            float2 v = *(const float2*)&g_C1[(size_t)(row0 + r) * 512 + 384 + dp];
            v.x = v.x > 0.f ? v.x : expm1f(v.x);
            v.y = v.y > 0.f ? v.y : expm1f(v.y);
            __nv_bfloat16 hx = __float2bfloat16(v.x), hy = __float2bfloat16(v.y);
            size_t idx = (size_t)(row0 + r) * 256 + dp;
            *(__nv_bfloat162*)&g_h_hi[idx] = __nv_bfloat162(hx, hy);
            *(__nv_bfloat162*)&g_h_lo[idx] =
                __nv_bfloat162(__float2bfloat16(v.x - __bfloat162float(hx)),
                               __float2bfloat16(v.y - __bfloat162float(hy)));
        }
    }
    __syncthreads();
    int h = t >> 5, r = t & 31;
    if (row0 + r >= NN) return;
    float q[HDIM];
    float diag = 0.f;
#pragma unroll
    for (int d4 = 0; d4 < 4; d4++) {
        float4 v = *(const float4*)&qs[r][h * 16 + d4 * 4];
        q[d4 * 4] = v.x * 0.5f; q[d4 * 4 + 1] = v.y * 0.5f;
        q[d4 * 4 + 2] = v.z * 0.5f; q[d4 * 4 + 3] = v.w * 0.5f;
    }
#pragma unroll
    for (int d = 0; d < HDIM; d++) diag += q[d] * q[d];
    diag *= 0.5f;
    float dash[NBF];
    float qmax = -3e38f;
#pragma unroll
    for (int m = 0; m < NBF; m++) {
        float sv = 0.f;
#pragma unroll
        for (int d4 = 0; d4 < 4; d4++) {
            float4 p = *(const float4*)&proj_s[m * 16 + d4 * 4];
            sv += q[d4 * 4] * p.x + q[d4 * 4 + 1] * p.y + q[d4 * 4 + 2] * p.z + q[d4 * 4 + 3] * p.w;
        }
        dash[m] = sv;
        qmax = fmaxf(qmax, sv);
    }
    float den = 0.f;
    float outv[HDIM];
#pragma unroll
    for (int d = 0; d < HDIM; d++) outv[d] = 0.f;
    const float ratio = rsqrtf((float)NBF);
#pragma unroll
    for (int m = 0; m < NBF; m++) {
        float qp = ratio * (fexp(dash[m] - diag - qmax) + EPSV);
        den += qp * kcum_s[h * NBF + m];
#pragma unroll
        for (int d4 = 0; d4 < 4; d4++) {
            float4 cv = *(const float4*)&ctxr[h][m * 16 + d4 * 4];
            outv[d4 * 4] += qp * cv.x; outv[d4 * 4 + 1] += qp * cv.y;
            outv[d4 * 4 + 2] += qp * cv.z; outv[d4 * 4 + 3] += qp * cv.w;
        }
    }
    float dinv = 1.f / den;
    size_t hbase = (size_t)(row0 + r) * 256 + HIDDIM + h * HDIM;
#pragma unroll
    for (int d = 0; d < HDIM; d += 2) {
        float x = outv[d] * dinv, y = outv[d + 1] * dinv;
        x = x > 0.f ? x : expm1f(x);
        y = y > 0.f ? y : expm1f(y);
        __nv_bfloat16 hx = __float2bfloat16(x), hy = __float2bfloat16(y);
        *(__nv_bfloat162*)&g_h_hi[hbase + d] = __nv_bfloat162(hx, hy);
        *(__nv_bfloat162*)&g_h_lo[hbase + d] =
            __nv_bfloat162(__float2bfloat16(x - __bfloat162float(hx)),
                           __float2bfloat16(y - __bfloat162float(hy)));
    }
}

// ---------------- APPNP graph prep ----------------
__global__ void deg_kernel(const int* __restrict__ col) {
    int e = blockIdx.x * blockDim.x + threadIdx.x;
    if (e < NEDGE) atomicAdd(&g_cnt[col[e]], 1);
}

__global__ __launch_bounds__(1024) void scan_kernel() {
    __shared__ int wsum[32];
    __shared__ int carry_s;
    int t = threadIdx.x;
    int lane = t & 31, wid = t >> 5;
    if (t == 0) carry_s = 0;
    __syncthreads();
    for (int base = 0; base < NN; base += 1024) {
        int i = base + t;
        int v = (i < NN) ? g_cnt[i] : 0;
        int x = v;
#pragma unroll
        for (int o = 1; o < 32; o <<= 1) {
            int y = __shfl_up_sync(0xffffffffu, x, o);
            if (lane >= o) x += y;
        }
        if (lane == 31) wsum[wid] = x;
        __syncthreads();
        if (wid == 0) {
            int s = wsum[lane];
#pragma unroll
            for (int o = 1; o < 32; o <<= 1) {
                int y = __shfl_up_sync(0xffffffffu, s, o);
                if (lane >= o) s += y;
            }
            wsum[lane] = s;
        }
        __syncthreads();
        int incl = x + (wid > 0 ? wsum[wid - 1] : 0);
        int carry = carry_s;
        if (i < NN) {
            int off = carry + incl - v;
            g_off[i] = off;
            g_cursor[i] = off;
            g_dis[i] = rsqrtf((float)(v + 1));
        }
        __syncthreads();
        if (t == 1023) carry_s = carry + incl;
        __syncthreads();
    }
    if (t == 0) g_off[NN] = carry_s;
}

__global__ void fill_kernel(const int* __restrict__ row, const int* __restrict__ col) {
    int e = blockIdx.x * blockDim.x + threadIdx.x;
    if (e >= NEDGE) return;
    int r = row[e], cl = col[e];
    int pos = atomicAdd(&g_cursor[cl], 1);
    g_csr[pos] = make_int2(r, __float_as_int(g_dis[r] * g_dis[cl]));
}

// ---------------- APPNP hop: 4 nodes per warp (8 lanes each), 32-deep MLP --------
template <bool LAST>
__global__ __launch_bounds__(256) void hop_kernel(int stage, float* __restrict__ out,
                                                  int out_size) {
    int gwarp = blockIdx.x * 8 + (threadIdx.x >> 5);
    int lane = threadIdx.x & 31;
    int sub = lane >> 3, li = lane & 7;      // 4 nodes per warp, 8 lanes per node
    int node = gwarp * 4 + sub;
    bool valid = node < NN;
    const __half* src = (stage == 0) ? g_x0h : ((stage & 1) ? g_ha : g_hb);
    __half* dst = (stage & 1) ? g_hb : g_ha;
    int s = 0, e = 0;
    if (valid) { s = g_off[node]; e = g_off[node + 1]; }
    int deg = e - s;
    int mdeg = deg;
#pragma unroll
    for (int o = 16; o > 0; o >>= 1) mdeg = max(mdeg, __shfl_xor_sync(0xffffffffu, mdeg, o));
    float di = valid ? g_dis[node] : 0.f;
    float4 x0a = make_float4(0.f, 0.f, 0.f, 0.f);
    float4 x0b = make_float4(0.f, 0.f, 0.f, 0.f);
    float a[8];
    {
        uint4 sv = make_uint4(0u, 0u, 0u, 0u);
        if (valid) {
            x0a = *(const float4*)&g_x0[(size_t)node * 64 + li * 8];
            x0b = *(const float4*)&g_x0[(size_t)node * 64 + li * 8 + 4];
            sv = *(const uint4*)&src[(size_t)node * 64 + li * 8];
        }
        float2 p0 = __half22float2(*(__half2*)&sv.x);
        float2 p1 = __half22float2(*(__half2*)&sv.y);
        float2 p2 = __half22float2(*(__half2*)&sv.z);
        float2 p3 = __half22float2(*(__half2*)&sv.w);
        float dd = di * di;
        a[0] = dd * p0.x; a[1] = dd * p0.y; a[2] = dd * p1.x; a[3] = dd * p1.y;
        a[4] = dd * p2.x; a[5] = dd * p2.y; a[6] = dd * p3.x; a[7] = dd * p3.y;
    }
    for (int jj = 0; jj < mdeg; jj += 8) {
        int2 ce[8];
#pragma unroll
        for (int u = 0; u < 8; u++)
            ce[u] = (jj + u < deg) ? g_csr[s + jj + u] : make_int2(0, 0);
#pragma unroll
        for (int u = 0; u < 8; u++) {
            if (jj + u < deg) {
                float wt = __int_as_float(ce[u].y);
                uint4 v = *(const uint4*)&src[(size_t)ce[u].x * 64 + li * 8];
                float2 p0 = __half22float2(*(__half2*)&v.x);
                float2 p1 = __half22float2(*(__half2*)&v.y);
                float2 p2 = __half22float2(*(__half2*)&v.z);
                float2 p3 = __half22float2(*(__half2*)&v.w);
                a[0] += wt * p0.x; a[1] += wt * p0.y; a[2] += wt * p1.x; a[3] += wt * p1.y;
                a[4] += wt * p2.x; a[5] += wt * p2.y; a[6] += wt * p3.x; a[7] += wt * p3.y;
            }
        }
    }
    float r[8];
    r[0] = (1.f - ALPHAV) * a[0] + ALPHAV * x0a.x;
    r[1] = (1.f - ALPHAV) * a[1] + ALPHAV * x0a.y;
    r[2] = (1.f - ALPHAV) * a[2] + ALPHAV * x0a.z;
    r[3] = (1.f - ALPHAV) * a[3] + ALPHAV * x0a.w;
    r[4] = (1.f - ALPHAV) * a[4] + ALPHAV * x0b.x;
    r[5] = (1.f - ALPHAV) * a[5] + ALPHAV * x0b.y;
    r[6] = (1.f - ALPHAV) * a[6] + ALPHAV * x0b.z;
    r[7] = (1.f - ALPHAV) * a[7] + ALPHAV * x0b.w;
    if (!valid) return;
    if (!LAST) {
        uint4 o4;
        *(__half2*)&o4.x = __floats2half2_rn(r[0], r[1]);
        *(__half2*)&o4.y = __floats2half2_rn(r[2], r[3]);
        *(__half2*)&o4.z = __floats2half2_rn(r[4], r[5]);
        *(__half2*)&o4.w = __floats2half2_rn(r[6], r[7]);
        *(uint4*)&dst[(size_t)node * 64 + li * 8] = o4;
    } else {
        // log_softmax within 8-lane group (8 values per lane)
        float mx = r[0];
#pragma unroll
        for (int u = 1; u < 8; u++) mx = fmaxf(mx, r[u]);
#pragma unroll
        for (int o = 4; o > 0; o >>= 1) mx = fmaxf(mx, __shfl_xor_sync(0xffffffffu, mx, o));
        float ss = 0.f;
#pragma unroll
        for (int u = 0; u < 8; u++) ss += __expf(r[u] - mx);
#pragma unroll
        for (int o = 4; o > 0; o >>= 1) ss += __shfl_xor_sync(0xffffffffu, ss, o);
        float lse = mx + logf(ss);
        int i0 = node * 64 + li * 8;
        if (i0 + 7 < out_size) {
            *(float4*)&out[i0] = make_float4(r[0] - lse, r[1] - lse, r[2] - lse, r[3] - lse);
            *(float4*)&out[i0 + 4] = make_float4(r[4] - lse, r[5] - lse, r[6] - lse, r[7] - lse);
        }
        int j0 = NN * 64 + i0;
        if (j0 + 7 < out_size) {
            *(float4*)&out[j0] = make_float4(r[0], r[1], r[2], r[3]);
            *(float4*)&out[j0 + 4] = make_float4(r[4], r[5], r[6], r[7]);
        }
    }
}

// ---------------- launch ----------------
extern "C" void kernel_launch(void* const* d_in, const int* in_sizes, int n_in,
                              void* d_out, int out_size) {
    if (n_in < 13) return;
    const float* data = (const float*)d_in[0];
    const int* ei = (const int*)d_in[1];
    const float* l1w = (const float*)d_in[2];
    const float* l1b = (const float*)d_in[3];
    const float* l2w = (const float*)d_in[4];
    const float* l2b = (const float*)d_in[5];
    const float* qw = (const float*)d_in[6];
    const float* qb = (const float*)d_in[7];
    const float* kw = (const float*)d_in[8];
    const float* kb = (const float*)d_in[9];
    const float* vw = (const float*)d_in[10];
    const float* vb = (const float*)d_in[11];
    const float* proj = (const float*)d_in[12];
    const int* row = ei;
    const int* col = ei + NEDGE;

    cudaFuncSetAttribute(hmma_gemm_kernel, cudaFuncAttributeMaxDynamicSharedMemorySize, HG_SMEM);
    cudaFuncSetAttribute(gemm2_kernel, cudaFuncAttributeMaxDynamicSharedMemorySize, G2_SMEM);

    prep_kernel<<<1024, 256>>>(data, qw, kw, vw, l1w, qb, kb, vb, l1b, l2w);

    dim3 g1((NN + 127) / 128, 4);
    hmma_gemm_kernel<<<g1, 256, HG_SMEM>>>();

    kmax_kernel<<<NTILES, 256>>>(proj);
    kp_acc_kernel<<<KPB, 352>>>(proj);
    attn_kernel<<<NTILES, 256>>>(proj);

    gemm2_kernel<<<(NN + 127) / 128, 256, G2_SMEM>>>(l2b);

    deg_kernel<<<(NEDGE + 255) / 256, 256>>>(col);
    scan_kernel<<<1, 1024>>>();
    fill_kernel<<<(NEDGE + 255) / 256, 256>>>(row, col);

    // 4 nodes per warp, 32 nodes per block
    int hop_grid = (NN + 31) / 32;
    for (int k = 0; k < 9; k++)
        hop_kernel<false><<<hop_grid, 256>>>(k, nullptr, 0);
    hop_kernel<true><<<hop_grid, 256>>>(9, (float*)d_out, out_size);
}

// round 12
// speedup vs baseline: 1.1339x; 1.1339x over previous
#include <cuda_runtime.h>
#include <cuda_bf16.h>
#include <cuda_fp16.h>
#include <math.h>
#include <stdint.h>

// ---------------- problem constants ----------------
#define NN     50000
#define FIN    256
#define HIDDIM 128
#define NHEADS 8
#define HDIM   16
#define NCLS   64
#define NEDGE  1250000
#define NBF    44
#define EPSV   1e-4f
#define ALPHAV 0.1f

#define NTILES ((NN + 31) / 32)

// ---------------- scratch (device globals; no runtime alloc) ----------------
__device__ float g_bias1[512];
__device__ __nv_bfloat16 g_Bt_hi[512 * 256];
__device__ __nv_bfloat16 g_Bt_lo[512 * 256];
__device__ __nv_bfloat16 g_B2_hi[64 * 256];
__device__ __nv_bfloat16 g_B2_lo[64 * 256];
__device__ __nv_bfloat16 g_A_hi[(size_t)NN * 256];
__device__ __nv_bfloat16 g_A_lo[(size_t)NN * 256];
__device__ float g_C1[(size_t)NN * 512];
__device__ float g_kmax[NHEADS];
__device__ float g_kcum[NHEADS * NBF];
__device__ float g_ctx[NHEADS * HDIM * NBF];   // [h][d][m]
__device__ __nv_bfloat16 g_h_hi[(size_t)NN * 256];
__device__ __nv_bfloat16 g_h_lo[(size_t)NN * 256];
__device__ float  g_x0[(size_t)NN * NCLS];
__device__ __half g_x0h[(size_t)NN * NCLS];
__device__ __half g_ha[(size_t)NN * NCLS];
__device__ __half g_hb[(size_t)NN * NCLS];
__device__ int   g_cnt[NN];
__device__ int   g_off[NN + 1];
__device__ int   g_cursor[NN];
__device__ float g_dis[NN];
__device__ int2  g_csr[NEDGE];

// ---------------- PTX helpers ----------------
__device__ __forceinline__ uint32_t smem_u32(const void* p) {
    uint32_t a;
    asm("{ .reg .u64 t; cvta.to.shared.u64 t, %1; cvt.u32.u64 %0, t; }" : "=r"(a) : "l"(p));
    return a;
}
#define LDMX4(r0, r1, r2, r3, addr)                                          \
    asm volatile("ldmatrix.sync.aligned.m8n8.x4.shared.b16 {%0,%1,%2,%3}, [%4];" \
                 : "=r"(r0), "=r"(r1), "=r"(r2), "=r"(r3) : "r"(addr))
#define MMA16816(c, a, b0v, b1v)                                             \
    asm volatile("mma.sync.aligned.m16n8k16.row.col.f32.bf16.bf16.f32 "      \
                 "{%0,%1,%2,%3},{%4,%5,%6,%7},{%8,%9},{%0,%1,%2,%3};"        \
                 : "+f"((c)[0]), "+f"((c)[1]), "+f"((c)[2]), "+f"((c)[3])    \
                 : "r"((a)[0]), "r"((a)[1]), "r"((a)[2]), "r"((a)[3]),       \
                   "r"(b0v), "r"(b1v))
__device__ __forceinline__ void cp_async16(uint32_t saddr, const void* gaddr, uint32_t srcsize) {
    asm volatile("cp.async.cg.shared.global [%0], [%1], 16, %2;"
                 :: "r"(saddr), "l"(gaddr), "r"(srcsize) : "memory");
}
#define CP_COMMIT() asm volatile("cp.async.commit_group;" ::: "memory")
#define CP_WAIT0()  asm volatile("cp.async.wait_group 0;" ::: "memory")

// ---------------- misc helpers ----------------
__device__ __forceinline__ void atomicMaxFloat(float* addr, float val) {
    int* ia = (int*)addr;
    int old = *ia;
    while (__int_as_float(old) < val) {
        int assumed = old;
        old = atomicCAS(ia, assumed, __float_as_int(val));
        if (old == assumed) break;
    }
}

__device__ __forceinline__ float fexp(float x) {
    float y = fmaxf(x * 1.44269504f, -125.0f);
    float z = y + 12582912.0f;
    int   n = __float_as_int(z) - 0x4B400000;
    float f = y - (z - 12582912.0f);
    float q = 0.00133335581f;
    q = q * f + 0.00961812911f;
    q = q * f + 0.0555041087f;
    q = q * f + 0.240226507f;
    q = q * f + 0.693147181f;
    q = q * f + 1.0f;
    return q * __int_as_float((n + 127) << 23);
}

// ---------------- prep: pack weights + split data + init (fused) ----------------
__global__ __launch_bounds__(256) void prep_kernel(
    const float* __restrict__ data,
    const float* __restrict__ qw, const float* __restrict__ kw,
    const float* __restrict__ vw, const float* __restrict__ l1w,
    const float* __restrict__ qb, const float* __restrict__ kb,
    const float* __restrict__ vb, const float* __restrict__ l1b,
    const float* __restrict__ l2w) {
    int gt = blockIdx.x * 256 + threadIdx.x;
    int NT = gridDim.x * 256;
    if (gt < NHEADS) g_kmax[gt] = -3e38f;
    for (int i = gt; i < NHEADS * NBF; i += NT) g_kcum[i] = 0.f;
    for (int i = gt; i < NHEADS * HDIM * NBF; i += NT) g_ctx[i] = 0.f;
    for (int i = gt; i < NN; i += NT) g_cnt[i] = 0;
    for (int i = gt; i < 512 * 256; i += NT) {
        int n = i >> 8, k = i & 255;
        const float* src = (n < 128) ? qw : (n < 256) ? kw : (n < 384) ? vw : l1w;
        float w = src[k * 128 + (n & 127)];
        __nv_bfloat16 hi = __float2bfloat16(w);
        g_Bt_hi[i] = hi;
        g_Bt_lo[i] = __float2bfloat16(w - __bfloat162float(hi));
    }
    if (gt < 512) {
        const float* sb = (gt < 128) ? qb : (gt < 256) ? kb : (gt < 384) ? vb : l1b;
        g_bias1[gt] = sb[gt & 127];
    }
    for (int i = gt; i < 64 * 256; i += NT) {
        int n = i >> 8, k = i & 255;
        float w = l2w[k * 64 + n];
        __nv_bfloat16 hi = __float2bfloat16(w);
        g_B2_hi[i] = hi;
        g_B2_lo[i] = __float2bfloat16(w - __bfloat162float(hi));
    }
    for (int i4 = gt; i4 < NN * 64; i4 += NT) {
        size_t base = (size_t)i4 * 4;
        float4 v = *(const float4*)&data[base];
        __nv_bfloat16 h0 = __float2bfloat16(v.x), h1 = __float2bfloat16(v.y);
        __nv_bfloat16 h2 = __float2bfloat16(v.z), h3 = __float2bfloat16(v.w);
        __nv_bfloat162* ph = (__nv_bfloat162*)&g_A_hi[base];
        ph[0] = __nv_bfloat162(h0, h1);
        ph[1] = __nv_bfloat162(h2, h3);
        __nv_bfloat162* pl = (__nv_bfloat162*)&g_A_lo[base];
        pl[0] = __nv_bfloat162(__float2bfloat16(v.x - __bfloat162float(h0)),
                               __float2bfloat16(v.y - __bfloat162float(h1)));
        pl[1] = __nv_bfloat162(__float2bfloat16(v.z - __bfloat162float(h2)),
                               __float2bfloat16(v.w - __bfloat162float(h3)));
    }
}

// ---------------- HMMA split-bf16 GEMM1 ----------------
#define HG_SMEM 65536
__global__ __launch_bounds__(256) void hmma_gemm_kernel() {
    extern __shared__ char smem[];
    const uint32_t sb = smem_u32(smem);
    const int t = threadIdx.x;
    const int w = t >> 5;
    const int lane = t & 31;
    const int wm = w >> 1, wn = w & 1;
    const int bm = blockIdx.x * 128;
    const int bn = blockIdx.y * 128;
    const uint32_t AH = 0, AL = 16384, BH = 32768, BL = 49152;

    float acc[2][8][4];
#pragma unroll
    for (int i = 0; i < 2; i++)
#pragma unroll
        for (int j = 0; j < 8; j++)
#pragma unroll
            for (int k = 0; k < 4; k++) acc[i][j][k] = 0.f;

    const int srow = t >> 3;
    const int schk = t & 7;

    for (int c = 0; c < 4; c++) {
        const int k0 = c * 64;
        if (c) __syncthreads();
#pragma unroll
        for (int rep = 0; rep < 4; rep++) {
            int row = rep * 32 + srow;
            uint32_t so = (uint32_t)(row * 128 + ((schk ^ (row & 7)) << 4));
            bool in = (bm + row) < NN;
            uint32_t asz = in ? 16u : 0u;
            size_t ga = (size_t)(in ? (bm + row) : 0) * 256 + k0 + schk * 8;
            cp_async16(sb + AH + so, &g_A_hi[ga], asz);
            cp_async16(sb + AL + so, &g_A_lo[ga], asz);
            size_t gb = (size_t)(bn + row) * 256 + k0 + schk * 8;
            cp_async16(sb + BH + so, &g_Bt_hi[gb], 16u);
            cp_async16(sb + BL + so, &g_Bt_lo[gb], 16u);
        }
        CP_COMMIT();
        CP_WAIT0();
        __syncthreads();

#pragma unroll
        for (int ks = 0; ks < 4; ks++) {
            uint32_t ah[2][4], al[2][4], bh[4][4], bl[4][4];
            int lr = lane & 15;
            int kh = lane >> 4;
            int chunk = ks * 2 + kh;
#pragma unroll
            for (int im = 0; im < 2; im++) {
                int row = wm * 32 + im * 16 + lr;
                uint32_t so = (uint32_t)(row * 128 + ((chunk ^ (row & 7)) << 4));
                LDMX4(ah[im][0], ah[im][1], ah[im][2], ah[im][3], sb + AH + so);
                LDMX4(al[im][0], al[im][1], al[im][2], al[im][3], sb + AL + so);
            }
#pragma unroll
            for (int in = 0; in < 4; in++) {
                int row = wn * 64 + in * 16 + lr;
                uint32_t so = (uint32_t)(row * 128 + ((chunk ^ (row & 7)) << 4));
                LDMX4(bh[in][0], bh[in][1], bh[in][2], bh[in][3], sb + BH + so);
                LDMX4(bl[in][0], bl[in][1], bl[in][2], bl[in][3], sb + BL + so);
            }
#pragma unroll
            for (int im = 0; im < 2; im++) {
#pragma unroll
                for (int in = 0; in < 4; in++) {
                    MMA16816(acc[im][2 * in],     ah[im], bh[in][0], bh[in][2]);
                    MMA16816(acc[im][2 * in + 1], ah[im], bh[in][1], bh[in][3]);
                    MMA16816(acc[im][2 * in],     ah[im], bl[in][0], bl[in][2]);
                    MMA16816(acc[im][2 * in + 1], ah[im], bl[in][1], bl[in][3]);
                    MMA16816(acc[im][2 * in],     al[im], bh[in][0], bh[in][2]);
                    MMA16816(acc[im][2 * in + 1], al[im], bh[in][1], bh[in][3]);
                }
            }
        }
    }
    int gid = lane >> 2, tig = lane & 3;
#pragma unroll
    for (int im = 0; im < 2; im++) {
        int m0 = bm + wm * 32 + im * 16 + gid;
#pragma unroll
        for (int s = 0; s < 8; s++) {
            int n = bn + wn * 64 + s * 8 + tig * 2;
            float b0 = g_bias1[n], b1 = g_bias1[n + 1];
            if (m0 < NN) {
                float2 v = make_float2(acc[im][s][0] + b0, acc[im][s][1] + b1);
                *(float2*)&g_C1[(size_t)m0 * 512 + n] = v;
            }
            if (m0 + 8 < NN) {
                float2 v = make_float2(acc[im][s][2] + b0, acc[im][s][3] + b1);
                *(float2*)&g_C1[(size_t)(m0 + 8) * 512 + n] = v;
            }
        }
    }
}

// ---------------- HMMA split-bf16 GEMM2 ----------------
#define G2_SMEM (16384 * 2 + 16384)
__global__ __launch_bounds__(256) void gemm2_kernel(const float* __restrict__ bext) {
    extern __shared__ char smem[];
    const uint32_t sb = smem_u32(smem);
    const int t = threadIdx.x;
    const int w = t >> 5;
    const int lane = t & 31;
    const int wm = w >> 1, wn = w & 1;
    const int bm = blockIdx.x * 128;
    const uint32_t AH = 0, AL = 16384, BH = 32768, BL = 40960;

    float acc[2][4][4];
#pragma unroll
    for (int i = 0; i < 2; i++)
#pragma unroll
        for (int j = 0; j < 4; j++)
#pragma unroll
            for (int k = 0; k < 4; k++) acc[i][j][k] = 0.f;

    const int srow = t >> 3;
    const int schk = t & 7;

    for (int c = 0; c < 4; c++) {
        const int k0 = c * 64;
        if (c) __syncthreads();
#pragma unroll
        for (int rep = 0; rep < 4; rep++) {
            int row = rep * 32 + srow;
            uint32_t so = (uint32_t)(row * 128 + ((schk ^ (row & 7)) << 4));
            bool in = (bm + row) < NN;
            uint32_t asz = in ? 16u : 0u;
            size_t ga = (size_t)(in ? (bm + row) : 0) * 256 + k0 + schk * 8;
            cp_async16(sb + AH + so, &g_h_hi[ga], asz);
            cp_async16(sb + AL + so, &g_h_lo[ga], asz);
        }
#pragma unroll
        for (int rep = 0; rep < 2; rep++) {
            int row = rep * 32 + srow;
            uint32_t so = (uint32_t)(row * 128 + ((schk ^ (row & 7)) << 4));
            size_t gb = (size_t)row * 256 + k0 + schk * 8;
            cp_async16(sb + BH + so, &g_B2_hi[gb], 16u);
            cp_async16(sb + BL + so, &g_B2_lo[gb], 16u);
        }
        CP_COMMIT();
        CP_WAIT0();
        __syncthreads();
#pragma unroll
        for (int ks = 0; ks < 4; ks++) {
            uint32_t ah[2][4], al[2][4], bh[2][4], bl[2][4];
            int lr = lane & 15;
            int kh = lane >> 4;
            int chunk = ks * 2 + kh;
#pragma unroll
            for (int im = 0; im < 2; im++) {
                int row = wm * 32 + im * 16 + lr;
                uint32_t so = (uint32_t)(row * 128 + ((chunk ^ (row & 7)) << 4));
                LDMX4(ah[im][0], ah[im][1], ah[im][2], ah[im][3], sb + AH + so);
                LDMX4(al[im][0], al[im][1], al[im][2], al[im][3], sb + AL + so);
            }
#pragma unroll
            for (int in = 0; in < 2; in++) {
                int row = wn * 32 + in * 16 + lr;
                uint32_t so = (uint32_t)(row * 128 + ((chunk ^ (row & 7)) << 4));
                LDMX4(bh[in][0], bh[in][1], bh[in][2], bh[in][3], sb + BH + so);
                LDMX4(bl[in][0], bl[in][1], bl[in][2], bl[in][3], sb + BL + so);
            }
#pragma unroll
            for (int im = 0; im < 2; im++) {
#pragma unroll
                for (int in = 0; in < 2; in++) {
                    MMA16816(acc[im][2 * in],     ah[im], bh[in][0], bh[in][2]);
                    MMA16816(acc[im][2 * in + 1], ah[im], bh[in][1], bh[in][3]);
                    MMA16816(acc[im][2 * in],     ah[im], bl[in][0], bl[in][2]);
                    MMA16816(acc[im][2 * in + 1], ah[im], bl[in][1], bl[in][3]);
                    MMA16816(acc[im][2 * in],     al[im], bh[in][0], bh[in][2]);
                    MMA16816(acc[im][2 * in + 1], al[im], bh[in][1], bh[in][3]);
                }
            }
        }
    }
    int gid = lane >> 2, tig = lane & 3;
#pragma unroll
    for (int im = 0; im < 2; im++) {
        int m0 = bm + wm * 32 + im * 16 + gid;
#pragma unroll
        for (int s = 0; s < 4; s++) {
            int n = wn * 32 + s * 8 + tig * 2;
            float b0 = bext[n], b1 = bext[n + 1];
            if (m0 < NN) {
                float x = acc[im][s][0] + b0, y = acc[im][s][1] + b1;
                x = x > 0.f ? x : expm1f(x);
                y = y > 0.f ? y : expm1f(y);
                *(float2*)&g_x0[(size_t)m0 * 64 + n] = make_float2(x, y);
                *(__half2*)&g_x0h[(size_t)m0 * 64 + n] = __floats2half2_rn(x, y);
            }
            if (m0 + 8 < NN) {
                float x = acc[im][s][2] + b0, y = acc[im][s][3] + b1;
                x = x > 0.f ? x : expm1f(x);
                y = y > 0.f ? y : expm1f(y);
                *(float2*)&g_x0[(size_t)(m0 + 8) * 64 + n] = make_float2(x, y);
                *(__half2*)&g_x0h[(size_t)(m0 + 8) * 64 + n] = __floats2half2_rn(x, y);
            }
        }
    }
}

// ---------------- performer: kmax (row-major tile, LDS.128) ----------------
__global__ __launch_bounds__(256) void kmax_kernel(const float* __restrict__ proj) {
    __shared__ float ks[32][132];
    __shared__ float proj_s[NBF * HDIM];
    int t = threadIdx.x;
    int row0 = blockIdx.x * 32;
    for (int i = t; i < NBF * HDIM; i += 256) proj_s[i] = proj[i];
    for (int i = t; i < 32 * 32; i += 256) {
        int r = i >> 5, c4 = i & 31;
        float4 v = make_float4(0.f, 0.f, 0.f, 0.f);
        if (row0 + r < NN) v = *(const float4*)&g_C1[(size_t)(row0 + r) * 512 + 128 + c4 * 4];
        *(float4*)&ks[r][c4 * 4] = v;
    }
    __syncthreads();
    int h = t >> 5, r = t & 31;
    float mx = -3e38f;
    if (row0 + r < NN) {
        float k[HDIM];
#pragma unroll
        for (int d4 = 0; d4 < 4; d4++) {
            float4 v = *(const float4*)&ks[r][h * 16 + d4 * 4];
            k[d4 * 4] = v.x * 0.5f; k[d4 * 4 + 1] = v.y * 0.5f;
            k[d4 * 4 + 2] = v.z * 0.5f; k[d4 * 4 + 3] = v.w * 0.5f;
        }
#pragma unroll
        for (int m = 0; m < NBF; m++) {
            float s = 0.f;
#pragma unroll
            for (int d4 = 0; d4 < 4; d4++) {
                float4 p = *(const float4*)&proj_s[m * 16 + d4 * 4];
                s += k[d4 * 4] * p.x + k[d4 * 4 + 1] * p.y + k[d4 * 4 + 2] * p.z + k[d4 * 4 + 3] * p.w;
            }
            mx = fmaxf(mx, s);
        }
    }
#pragma unroll
    for (int o = 16; o > 0; o >>= 1) mx = fmaxf(mx, __shfl_xor_sync(0xffffffffu, mx, o));
    if (r == 0) atomicMaxFloat(&g_kmax[h], mx);
}

// ---------------- performer: kp (row-major tile, hoisted diag, LDS.128) ----------
#define KPB 444
__global__ __launch_bounds__(352) void kp_acc_kernel(const float* __restrict__ proj) {
    __shared__ float s[32][264];
    __shared__ float diag_s[32][8];
    int t = threadIdx.x;
    int h = t / NBF, m = t - h * NBF;
    float pm[HDIM];
#pragma unroll
    for (int d = 0; d < HDIM; d++) pm[d] = proj[m * HDIM + d];
    float kmaxh = g_kmax[h];
    const float ratio = rsqrtf((float)NBF);
    float ctx[HDIM];
    float kc = 0.f;
#pragma unroll
    for (int d = 0; d < HDIM; d++) ctx[d] = 0.f;

    for (int tile = blockIdx.x; tile < NTILES; tile += gridDim.x) {
        int row0 = tile * 32;
        __syncthreads();
        for (int i = t; i < 32 * 64; i += 352) {
            int r = i >> 6, c4 = i & 63;
            float4 v = make_float4(0.f, 0.f, 0.f, 0.f);
            if (row0 + r < NN) v = *(const float4*)&g_C1[(size_t)(row0 + r) * 512 + 128 + c4 * 4];
            *(float4*)&s[r][c4 * 4] = v;
        }
        __syncthreads();
        if (t < 256) {
            int rr = t >> 3, hh = t & 7;
            float sum = 0.f;
#pragma unroll
            for (int d4 = 0; d4 < 4; d4++) {
                float4 v = *(const float4*)&s[rr][hh * 16 + d4 * 4];
                sum += v.x * v.x + v.y * v.y + v.z * v.z + v.w * v.w;
            }
            diag_s[rr][hh] = 0.125f * sum;
        }
        __syncthreads();
        int rmax = min(32, NN - row0);
        for (int r = 0; r < rmax; r++) {
            float draw = 0.f;
#pragma unroll
            for (int d4 = 0; d4 < 4; d4++) {
                float4 v = *(const float4*)&s[r][h * 16 + d4 * 4];
                draw += v.x * pm[d4 * 4] + v.y * pm[d4 * 4 + 1] + v.z * pm[d4 * 4 + 2] + v.w * pm[d4 * 4 + 3];
            }
            float kpv = ratio * (fexp(0.5f * draw - diag_s[r][h] - kmaxh) + EPSV);
            kc += kpv;
#pragma unroll
            for (int d4 = 0; d4 < 4; d4++) {
                float4 v = *(const float4*)&s[r][128 + h * 16 + d4 * 4];
                ctx[d4 * 4] += kpv * v.x; ctx[d4 * 4 + 1] += kpv * v.y;
                ctx[d4 * 4 + 2] += kpv * v.z; ctx[d4 * 4 + 3] += kpv * v.w;
            }
        }
    }
    atomicAdd(&g_kcum[h * NBF + m], kc);
#pragma unroll
    for (int d = 0; d < HDIM; d++) atomicAdd(&g_ctx[(h * HDIM + d) * NBF + m], ctx[d]);
}

// ---------------- attention (row-major q tile, ctx [h][m][d], LDS.128) -----------
__global__ __launch_bounds__(256) void attn_kernel(const float* __restrict__ proj) {
    __shared__ float qs[32][132];
    __shared__ float proj_s[NBF * HDIM];
    __shared__ float kcum_s[NHEADS * NBF];
    __shared__ float ctxr[NHEADS][NBF * HDIM];
    int t = threadIdx.x;
    int row0 = blockIdx.x * 32;
    for (int i = t; i < NBF * HDIM; i += 256) proj_s[i] = proj[i];
    for (int i = t; i < NHEADS * NBF; i += 256) kcum_s[i] = g_kcum[i];
    for (int i = t; i < NHEADS * NBF * HDIM; i += 256) {
        int hh = i / (NBF * HDIM);
        int rem = i - hh * NBF * HDIM;
        int mm = rem >> 4, dd = rem & 15;
        ctxr[hh][mm * 16 + dd] = g_ctx[(hh * HDIM + dd) * NBF + mm];
    }
    for (int i = t; i < 32 * 32; i += 256) {
        int r = i >> 5, c4 = i & 31;
        float4 v = make_float4(0.f, 0.f, 0.f, 0.f);
        if (row0 + r < NN) v = *(const float4*)&g_C1[(size_t)(row0 + r) * 512 + c4 * 4];
        *(float4*)&qs[r][c4 * 4] = v;
    }
    for (int i = t; i < 32 * 64; i += 256) {
        int r = i >> 6, dp = (i & 63) * 2;
        if (row0 + r < NN) {
            float2 v = *(const float2*)&g_C1[(size_t)(row0 + r) * 512 + 384 + dp];
            v.x = v.x > 0.f ? v.x : expm1f(v.x);
            v.y = v.y > 0.f ? v.y : expm1f(v.y);
            __nv_bfloat16 hx = __float2bfloat16(v.x), hy = __float2bfloat16(v.y);
            size_t idx = (size_t)(row0 + r) * 256 + dp;
            *(__nv_bfloat162*)&g_h_hi[idx] = __nv_bfloat162(hx, hy);
            *(__nv_bfloat162*)&g_h_lo[idx] =
                __nv_bfloat162(__float2bfloat16(v.x - __bfloat162float(hx)),
                               __float2bfloat16(v.y - __bfloat162float(hy)));
        }
    }
    __syncthreads();
    int h = t >> 5, r = t & 31;
    if (row0 + r >= NN) return;
    float q[HDIM];
    float diag = 0.f;
#pragma unroll
    for (int d4 = 0; d4 < 4; d4++) {
        float4 v = *(const float4*)&qs[r][h * 16 + d4 * 4];
        q[d4 * 4] = v.x * 0.5f; q[d4 * 4 + 1] = v.y * 0.5f;
        q[d4 * 4 + 2] = v.z * 0.5f; q[d4 * 4 + 3] = v.w * 0.5f;
    }
#pragma unroll
    for (int d = 0; d < HDIM; d++) diag += q[d] * q[d];
    diag *= 0.5f;
    float dash[NBF];
    float qmax = -3e38f;
#pragma unroll
    for (int m = 0; m < NBF; m++) {
        float sv = 0.f;
#pragma unroll
        for (int d4 = 0; d4 < 4; d4++) {
            float4 p = *(const float4*)&proj_s[m * 16 + d4 * 4];
            sv += q[d4 * 4] * p.x + q[d4 * 4 + 1] * p.y + q[d4 * 4 + 2] * p.z + q[d4 * 4 + 3] * p.w;
        }
        dash[m] = sv;
        qmax = fmaxf(qmax, sv);
    }
    float den = 0.f;
    float outv[HDIM];
#pragma unroll
    for (int d = 0; d < HDIM; d++) outv[d] = 0.f;
    const float ratio = rsqrtf((float)NBF);
#pragma unroll
    for (int m = 0; m < NBF; m++) {
        float qp = ratio * (fexp(dash[m] - diag - qmax) + EPSV);
        den += qp * kcum_s[h * NBF + m];
#pragma unroll
        for (int d4 = 0; d4 < 4; d4++) {
            float4 cv = *(const float4*)&ctxr[h][m * 16 + d4 * 4];
            outv[d4 * 4] += qp * cv.x; outv[d4 * 4 + 1] += qp * cv.y;
            outv[d4 * 4 + 2] += qp * cv.z; outv[d4 * 4 + 3] += qp * cv.w;
        }
    }
    float dinv = 1.f / den;
    size_t hbase = (size_t)(row0 + r) * 256 + HIDDIM + h * HDIM;
#pragma unroll
    for (int d = 0; d < HDIM; d += 2) {
        float x = outv[d] * dinv, y = outv[d + 1] * dinv;
        x = x > 0.f ? x : expm1f(x);
        y = y > 0.f ? y : expm1f(y);
        __nv_bfloat16 hx = __float2bfloat16(x), hy = __float2bfloat16(y);
        *(__nv_bfloat162*)&g_h_hi[hbase + d] = __nv_bfloat162(hx, hy);
        *(__nv_bfloat162*)&g_h_lo[hbase + d] =
            __nv_bfloat162(__float2bfloat16(x - __bfloat162float(hx)),
                           __float2bfloat16(y - __bfloat162float(hy)));
    }
}

// ---------------- APPNP graph prep ----------------
__global__ void deg_kernel(const int* __restrict__ col) {
    int e = blockIdx.x * blockDim.x + threadIdx.x;
    if (e < NEDGE) atomicAdd(&g_cnt[col[e]], 1);
}

__global__ __launch_bounds__(1024) void scan_kernel() {
    __shared__ int wsum[32];
    __shared__ int carry_s;
    int t = threadIdx.x;
    int lane = t & 31, wid = t >> 5;
    if (t == 0) carry_s = 0;
    __syncthreads();
    for (int base = 0; base < NN; base += 1024) {
        int i = base + t;
        int v = (i < NN) ? g_cnt[i] : 0;
        int x = v;
#pragma unroll
        for (int o = 1; o < 32; o <<= 1) {
            int y = __shfl_up_sync(0xffffffffu, x, o);
            if (lane >= o) x += y;
        }
        if (lane == 31) wsum[wid] = x;
        __syncthreads();
        if (wid == 0) {
            int s = wsum[lane];
#pragma unroll
            for (int o = 1; o < 32; o <<= 1) {
                int y = __shfl_up_sync(0xffffffffu, s, o);
                if (lane >= o) s += y;
            }
            wsum[lane] = s;
        }
        __syncthreads();
        int incl = x + (wid > 0 ? wsum[wid - 1] : 0);
        int carry = carry_s;
        if (i < NN) {
            int off = carry + incl - v;
            g_off[i] = off;
            g_cursor[i] = off;
            g_dis[i] = rsqrtf((float)(v + 1));
        }
        __syncthreads();
        if (t == 1023) carry_s = carry + incl;
        __syncthreads();
    }
    if (t == 0) g_off[NN] = carry_s;
}

__global__ void fill_kernel(const int* __restrict__ row, const int* __restrict__ col) {
    int e = blockIdx.x * blockDim.x + threadIdx.x;
    if (e >= NEDGE) return;
    int r = row[e], cl = col[e];
    int pos = atomicAdd(&g_cursor[cl], 1);
    g_csr[pos] = make_int2(r, __float_as_int(g_dis[r] * g_dis[cl]));
}

// ---------------- APPNP hop: 2 nodes per warp (16 lanes each), 16-deep MLP --------
template <bool LAST>
__global__ __launch_bounds__(256) void hop_kernel(int stage, float* __restrict__ out,
                                                  int out_size) {
    int gwarp = blockIdx.x * 8 + (threadIdx.x >> 5);
    int lane = threadIdx.x & 31;
    int sub = lane >> 4, li = lane & 15;
    int node = gwarp * 2 + sub;          // NN even; all nodes covered
    bool valid = node < NN;
    const __half* src = (stage == 0) ? g_x0h : ((stage & 1) ? g_ha : g_hb);
    __half* dst = (stage & 1) ? g_hb : g_ha;
    int s = 0, e = 0;
    if (valid) { s = g_off[node]; e = g_off[node + 1]; }
    int deg = e - s;
    int mdeg = deg;
#pragma unroll
    for (int o = 16; o > 0; o >>= 1) mdeg = max(mdeg, __shfl_xor_sync(0xffffffffu, mdeg, o));
    float di = valid ? g_dis[node] : 0.f;
    float4 x0v = make_float4(0.f, 0.f, 0.f, 0.f);
    float a0, a1, a2, a3;
    {
        uint2 sv = make_uint2(0u, 0u);
        if (valid) {
            x0v = *(const float4*)&g_x0[(size_t)node * 64 + li * 4];
            sv = *(const uint2*)&src[(size_t)node * 64 + li * 4];
        }
        float2 p0 = __half22float2(*(__half2*)&sv.x);
        float2 p1 = __half22float2(*(__half2*)&sv.y);
        float dd = di * di;
        a0 = dd * p0.x; a1 = dd * p0.y; a2 = dd * p1.x; a3 = dd * p1.y;
    }
    for (int jj = 0; jj < mdeg; jj += 8) {
        int2 ce[8];
#pragma unroll
        for (int u = 0; u < 8; u++)
            ce[u] = (jj + u < deg) ? g_csr[s + jj + u] : make_int2(0, 0);
#pragma unroll
        for (int u = 0; u < 8; u++) {
            if (jj + u < deg) {
                float wt = __int_as_float(ce[u].y);
                uint2 v = *(const uint2*)&src[(size_t)ce[u].x * 64 + li * 4];
                float2 p0 = __half22float2(*(__half2*)&v.x);
                float2 p1 = __half22float2(*(__half2*)&v.y);
                a0 += wt * p0.x; a1 += wt * p0.y; a2 += wt * p1.x; a3 += wt * p1.y;
            }
        }
    }
    float r0 = (1.f - ALPHAV) * a0 + ALPHAV * x0v.x;
    float r1 = (1.f - ALPHAV) * a1 + ALPHAV * x0v.y;
    float r2 = (1.f - ALPHAV) * a2 + ALPHAV * x0v.z;
    float r3 = (1.f - ALPHAV) * a3 + ALPHAV * x0v.w;
    if (!valid) return;
    if (!LAST) {
        uint2 o2;
        *(__half2*)&o2.x = __floats2half2_rn(r0, r1);
        *(__half2*)&o2.y = __floats2half2_rn(r2, r3);
        *(uint2*)&dst[(size_t)node * 64 + li * 4] = o2;
    } else {
        float mx = fmaxf(fmaxf(r0, r1), fmaxf(r2, r3));
#pragma unroll
        for (int o = 8; o > 0; o >>= 1) mx = fmaxf(mx, __shfl_xor_sync(0xffffffffu, mx, o));
        float ss = __expf(r0 - mx) + __expf(r1 - mx) + __expf(r2 - mx) + __expf(r3 - mx);
#pragma unroll
        for (int o = 8; o > 0; o >>= 1) ss += __shfl_xor_sync(0xffffffffu, ss, o);
        float lse = mx + logf(ss);
        int i0 = node * 64 + li * 4;
        if (i0 + 3 < out_size)
            *(float4*)&out[i0] = make_float4(r0 - lse, r1 - lse, r2 - lse, r3 - lse);
        int j0 = NN * 64 + i0;
        if (j0 + 3 < out_size)
            *(float4*)&out[j0] = make_float4(r0, r1, r2, r3);
    }
}

// ---------------- launch ----------------
extern "C" void kernel_launch(void* const* d_in, const int* in_sizes, int n_in,
                              void* d_out, int out_size) {
    if (n_in < 13) return;
    const float* data = (const float*)d_in[0];
    const int* ei = (const int*)d_in[1];
    const float* l1w = (const float*)d_in[2];
    const float* l1b = (const float*)d_in[3];
    const float* l2w = (const float*)d_in[4];
    const float* l2b = (const float*)d_in[5];
    const float* qw = (const float*)d_in[6];
    const float* qb = (const float*)d_in[7];
    const float* kw = (const float*)d_in[8];
    const float* kb = (const float*)d_in[9];
    const float* vw = (const float*)d_in[10];
    const float* vb = (const float*)d_in[11];
    const float* proj = (const float*)d_in[12];
    const int* row = ei;
    const int* col = ei + NEDGE;

    cudaFuncSetAttribute(hmma_gemm_kernel, cudaFuncAttributeMaxDynamicSharedMemorySize, HG_SMEM);
    cudaFuncSetAttribute(gemm2_kernel, cudaFuncAttributeMaxDynamicSharedMemorySize, G2_SMEM);

    prep_kernel<<<1024, 256>>>(data, qw, kw, vw, l1w, qb, kb, vb, l1b, l2w);

    dim3 g1((NN + 127) / 128, 4);
    hmma_gemm_kernel<<<g1, 256, HG_SMEM>>>();

    kmax_kernel<<<NTILES, 256>>>(proj);
    kp_acc_kernel<<<KPB, 352>>>(proj);
    attn_kernel<<<NTILES, 256>>>(proj);

    gemm2_kernel<<<(NN + 127) / 128, 256, G2_SMEM>>>(l2b);

    deg_kernel<<<(NEDGE + 255) / 256, 256>>>(col);
    scan_kernel<<<1, 1024>>>();
    fill_kernel<<<(NEDGE + 255) / 256, 256>>>(row, col);

    // 2 nodes per warp, 16 nodes per block
    int hop_grid = (NN + 15) / 16;
    for (int k = 0; k < 9; k++)
        hop_kernel<false><<<hop_grid, 256>>>(k, nullptr, 0);
    hop_kernel<true><<<hop_grid, 256>>>(9, (float*)d_out, out_size);
}

// round 13
// speedup vs baseline: 1.1373x; 1.0030x over previous
#include <cuda_runtime.h>
#include <cuda_bf16.h>
#include <cuda_fp16.h>
#include <math.h>
#include <stdint.h>

// ---------------- problem constants ----------------
#define NN     50000
#define FIN    256
#define HIDDIM 128
#define NHEADS 8
#define HDIM   16
#define NCLS   64
#define NEDGE  1250000
#define NBF    44
#define EPSV   1e-4f
#define ALPHAV 0.1f

#define NTILES ((NN + 31) / 32)

// ---------------- scratch (device globals; no runtime alloc) ----------------
__device__ float g_bias1[512];
__device__ __nv_bfloat16 g_Bt_hi[512 * 256];
__device__ __nv_bfloat16 g_Bt_lo[512 * 256];
__device__ __nv_bfloat16 g_B2_hi[64 * 256];
__device__ __nv_bfloat16 g_B2_lo[64 * 256];
__device__ __nv_bfloat16 g_A_hi[(size_t)NN * 256];
__device__ __nv_bfloat16 g_A_lo[(size_t)NN * 256];
__device__ float g_C1[(size_t)NN * 512];
__device__ float g_kmax[NHEADS];
__device__ float g_kcum[NHEADS * NBF];
__device__ float g_ctx[NHEADS * HDIM * NBF];   // [h][d][m]
__device__ __nv_bfloat16 g_h_hi[(size_t)NN * 256];
__device__ __nv_bfloat16 g_h_lo[(size_t)NN * 256];
__device__ float  g_x0[(size_t)NN * NCLS];
__device__ __half g_x0h[(size_t)NN * NCLS];
__device__ __half g_ha[(size_t)NN * NCLS];
__device__ __half g_hb[(size_t)NN * NCLS];
__device__ int   g_cnt[NN];
__device__ int   g_off[NN + 1];
__device__ int   g_cursor[NN];
__device__ float g_dis[NN];
__device__ int2  g_csr[NEDGE];

// ---------------- PTX helpers ----------------
__device__ __forceinline__ uint32_t smem_u32(const void* p) {
    uint32_t a;
    asm("{ .reg .u64 t; cvta.to.shared.u64 t, %1; cvt.u32.u64 %0, t; }" : "=r"(a) : "l"(p));
    return a;
}
#define LDMX4(r0, r1, r2, r3, addr)                                          \
    asm volatile("ldmatrix.sync.aligned.m8n8.x4.shared.b16 {%0,%1,%2,%3}, [%4];" \
                 : "=r"(r0), "=r"(r1), "=r"(r2), "=r"(r3) : "r"(addr))
#define MMA16816(c, a, b0v, b1v)                                             \
    asm volatile("mma.sync.aligned.m16n8k16.row.col.f32.bf16.bf16.f32 "      \
                 "{%0,%1,%2,%3},{%4,%5,%6,%7},{%8,%9},{%0,%1,%2,%3};"        \
                 : "+f"((c)[0]), "+f"((c)[1]), "+f"((c)[2]), "+f"((c)[3])    \
                 : "r"((a)[0]), "r"((a)[1]), "r"((a)[2]), "r"((a)[3]),       \
                   "r"(b0v), "r"(b1v))
__device__ __forceinline__ void cp_async16(uint32_t saddr, const void* gaddr, uint32_t srcsize) {
    asm volatile("cp.async.cg.shared.global [%0], [%1], 16, %2;"
                 :: "r"(saddr), "l"(gaddr), "r"(srcsize) : "memory");
}
#define CP_COMMIT() asm volatile("cp.async.commit_group;" ::: "memory")
#define CP_WAIT0()  asm volatile("cp.async.wait_group 0;" ::: "memory")

// ---------------- packed f32x2 helpers (FFMA2 on sm_103a) ----------------
typedef unsigned long long ull;
__device__ __forceinline__ ull pack2(float x, float y) {
    ull r; asm("mov.b64 %0, {%1, %2};" : "=l"(r) : "f"(x), "f"(y)); return r;
}
__device__ __forceinline__ void unpack2(ull v, float& x, float& y) {
    asm("mov.b64 {%0, %1}, %2;" : "=f"(x), "=f"(y) : "l"(v));
}
__device__ __forceinline__ ull fma2(ull a, ull b, ull c) {
    ull r; asm("fma.rn.f32x2 %0, %1, %2, %3;" : "=l"(r) : "l"(a), "l"(b), "l"(c)); return r;
}

// ---------------- misc helpers ----------------
__device__ __forceinline__ void atomicMaxFloat(float* addr, float val) {
    int* ia = (int*)addr;
    int old = *ia;
    while (__int_as_float(old) < val) {
        int assumed = old;
        old = atomicCAS(ia, assumed, __float_as_int(val));
        if (old == assumed) break;
    }
}

__device__ __forceinline__ float fexp(float x) {
    float y = fmaxf(x * 1.44269504f, -125.0f);
    float z = y + 12582912.0f;
    int   n = __float_as_int(z) - 0x4B400000;
    float f = y - (z - 12582912.0f);
    float q = 0.00133335581f;
    q = q * f + 0.00961812911f;
    q = q * f + 0.0555041087f;
    q = q * f + 0.240226507f;
    q = q * f + 0.693147181f;
    q = q * f + 1.0f;
    return q * __int_as_float((n + 127) << 23);
}

// ---------------- prep: pack weights + split data + init (fused) ----------------
__global__ __launch_bounds__(256) void prep_kernel(
    const float* __restrict__ data,
    const float* __restrict__ qw, const float* __restrict__ kw,
    const float* __restrict__ vw, const float* __restrict__ l1w,
    const float* __restrict__ qb, const float* __restrict__ kb,
    const float* __restrict__ vb, const float* __restrict__ l1b,
    const float* __restrict__ l2w) {
    int gt = blockIdx.x * 256 + threadIdx.x;
    int NT = gridDim.x * 256;
    if (gt < NHEADS) g_kmax[gt] = -3e38f;
    for (int i = gt; i < NHEADS * NBF; i += NT) g_kcum[i] = 0.f;
    for (int i = gt; i < NHEADS * HDIM * NBF; i += NT) g_ctx[i] = 0.f;
    for (int i = gt; i < NN; i += NT) g_cnt[i] = 0;
    for (int i = gt; i < 512 * 256; i += NT) {
        int n = i >> 8, k = i & 255;
        const float* src = (n < 128) ? qw : (n < 256) ? kw : (n < 384) ? vw : l1w;
        float w = src[k * 128 + (n & 127)];
        __nv_bfloat16 hi = __float2bfloat16(w);
        g_Bt_hi[i] = hi;
        g_Bt_lo[i] = __float2bfloat16(w - __bfloat162float(hi));
    }
    if (gt < 512) {
        const float* sb = (gt < 128) ? qb : (gt < 256) ? kb : (gt < 384) ? vb : l1b;
        g_bias1[gt] = sb[gt & 127];
    }
    for (int i = gt; i < 64 * 256; i += NT) {
        int n = i >> 8, k = i & 255;
        float w = l2w[k * 64 + n];
        __nv_bfloat16 hi = __float2bfloat16(w);
        g_B2_hi[i] = hi;
        g_B2_lo[i] = __float2bfloat16(w - __bfloat162float(hi));
    }
    for (int i4 = gt; i4 < NN * 64; i4 += NT) {
        size_t base = (size_t)i4 * 4;
        float4 v = *(const float4*)&data[base];
        __nv_bfloat16 h0 = __float2bfloat16(v.x), h1 = __float2bfloat16(v.y);
        __nv_bfloat16 h2 = __float2bfloat16(v.z), h3 = __float2bfloat16(v.w);
        __nv_bfloat162* ph = (__nv_bfloat162*)&g_A_hi[base];
        ph[0] = __nv_bfloat162(h0, h1);
        ph[1] = __nv_bfloat162(h2, h3);
        __nv_bfloat162* pl = (__nv_bfloat162*)&g_A_lo[base];
        pl[0] = __nv_bfloat162(__float2bfloat16(v.x - __bfloat162float(h0)),
                               __float2bfloat16(v.y - __bfloat162float(h1)));
        pl[1] = __nv_bfloat162(__float2bfloat16(v.z - __bfloat162float(h2)),
                               __float2bfloat16(v.w - __bfloat162float(h3)));
    }
}

// ---------------- HMMA split-bf16 GEMM1 ----------------
#define HG_SMEM 65536
__global__ __launch_bounds__(256) void hmma_gemm_kernel() {
    extern __shared__ char smem[];
    const uint32_t sb = smem_u32(smem);
    const int t = threadIdx.x;
    const int w = t >> 5;
    const int lane = t & 31;
    const int wm = w >> 1, wn = w & 1;
    const int bm = blockIdx.x * 128;
    const int bn = blockIdx.y * 128;
    const uint32_t AH = 0, AL = 16384, BH = 32768, BL = 49152;

    float acc[2][8][4];
#pragma unroll
    for (int i = 0; i < 2; i++)
#pragma unroll
        for (int j = 0; j < 8; j++)
#pragma unroll
            for (int k = 0; k < 4; k++) acc[i][j][k] = 0.f;

    const int srow = t >> 3;
    const int schk = t & 7;

    for (int c = 0; c < 4; c++) {
        const int k0 = c * 64;
        if (c) __syncthreads();
#pragma unroll
        for (int rep = 0; rep < 4; rep++) {
            int row = rep * 32 + srow;
            uint32_t so = (uint32_t)(row * 128 + ((schk ^ (row & 7)) << 4));
            bool in = (bm + row) < NN;
            uint32_t asz = in ? 16u : 0u;
            size_t ga = (size_t)(in ? (bm + row) : 0) * 256 + k0 + schk * 8;
            cp_async16(sb + AH + so, &g_A_hi[ga], asz);
            cp_async16(sb + AL + so, &g_A_lo[ga], asz);
            size_t gb = (size_t)(bn + row) * 256 + k0 + schk * 8;
            cp_async16(sb + BH + so, &g_Bt_hi[gb], 16u);
            cp_async16(sb + BL + so, &g_Bt_lo[gb], 16u);
        }
        CP_COMMIT();
        CP_WAIT0();
        __syncthreads();

#pragma unroll
        for (int ks = 0; ks < 4; ks++) {
            uint32_t ah[2][4], al[2][4], bh[4][4], bl[4][4];
            int lr = lane & 15;
            int kh = lane >> 4;
            int chunk = ks * 2 + kh;
#pragma unroll
            for (int im = 0; im < 2; im++) {
                int row = wm * 32 + im * 16 + lr;
                uint32_t so = (uint32_t)(row * 128 + ((chunk ^ (row & 7)) << 4));
                LDMX4(ah[im][0], ah[im][1], ah[im][2], ah[im][3], sb + AH + so);
                LDMX4(al[im][0], al[im][1], al[im][2], al[im][3], sb + AL + so);
            }
#pragma unroll
            for (int in = 0; in < 4; in++) {
                int row = wn * 64 + in * 16 + lr;
                uint32_t so = (uint32_t)(row * 128 + ((chunk ^ (row & 7)) << 4));
                LDMX4(bh[in][0], bh[in][1], bh[in][2], bh[in][3], sb + BH + so);
                LDMX4(bl[in][0], bl[in][1], bl[in][2], bl[in][3], sb + BL + so);
            }
#pragma unroll
            for (int im = 0; im < 2; im++) {
#pragma unroll
                for (int in = 0; in < 4; in++) {
                    MMA16816(acc[im][2 * in],     ah[im], bh[in][0], bh[in][2]);
                    MMA16816(acc[im][2 * in + 1], ah[im], bh[in][1], bh[in][3]);
                    MMA16816(acc[im][2 * in],     ah[im], bl[in][0], bl[in][2]);
                    MMA16816(acc[im][2 * in + 1], ah[im], bl[in][1], bl[in][3]);
                    MMA16816(acc[im][2 * in],     al[im], bh[in][0], bh[in][2]);
                    MMA16816(acc[im][2 * in + 1], al[im], bh[in][1], bh[in][3]);
                }
            }
        }
    }
    int gid = lane >> 2, tig = lane & 3;
#pragma unroll
    for (int im = 0; im < 2; im++) {
        int m0 = bm + wm * 32 + im * 16 + gid;
#pragma unroll
        for (int s = 0; s < 8; s++) {
            int n = bn + wn * 64 + s * 8 + tig * 2;
            float b0 = g_bias1[n], b1 = g_bias1[n + 1];
            if (m0 < NN) {
                float2 v = make_float2(acc[im][s][0] + b0, acc[im][s][1] + b1);
                *(float2*)&g_C1[(size_t)m0 * 512 + n] = v;
            }
            if (m0 + 8 < NN) {
                float2 v = make_float2(acc[im][s][2] + b0, acc[im][s][3] + b1);
                *(float2*)&g_C1[(size_t)(m0 + 8) * 512 + n] = v;
            }
        }
    }
}

// ---------------- HMMA split-bf16 GEMM2 ----------------
#define G2_SMEM (16384 * 2 + 16384)
__global__ __launch_bounds__(256) void gemm2_kernel(const float* __restrict__ bext) {
    extern __shared__ char smem[];
    const uint32_t sb = smem_u32(smem);
    const int t = threadIdx.x;
    const int w = t >> 5;
    const int lane = t & 31;
    const int wm = w >> 1, wn = w & 1;
    const int bm = blockIdx.x * 128;
    const uint32_t AH = 0, AL = 16384, BH = 32768, BL = 40960;

    float acc[2][4][4];
#pragma unroll
    for (int i = 0; i < 2; i++)
#pragma unroll
        for (int j = 0; j < 4; j++)
#pragma unroll
            for (int k = 0; k < 4; k++) acc[i][j][k] = 0.f;

    const int srow = t >> 3;
    const int schk = t & 7;

    for (int c = 0; c < 4; c++) {
        const int k0 = c * 64;
        if (c) __syncthreads();
#pragma unroll
        for (int rep = 0; rep < 4; rep++) {
            int row = rep * 32 + srow;
            uint32_t so = (uint32_t)(row * 128 + ((schk ^ (row & 7)) << 4));
            bool in = (bm + row) < NN;
            uint32_t asz = in ? 16u : 0u;
            size_t ga = (size_t)(in ? (bm + row) : 0) * 256 + k0 + schk * 8;
            cp_async16(sb + AH + so, &g_h_hi[ga], asz);
            cp_async16(sb + AL + so, &g_h_lo[ga], asz);
        }
#pragma unroll
        for (int rep = 0; rep < 2; rep++) {
            int row = rep * 32 + srow;
            uint32_t so = (uint32_t)(row * 128 + ((schk ^ (row & 7)) << 4));
            size_t gb = (size_t)row * 256 + k0 + schk * 8;
            cp_async16(sb + BH + so, &g_B2_hi[gb], 16u);
            cp_async16(sb + BL + so, &g_B2_lo[gb], 16u);
        }
        CP_COMMIT();
        CP_WAIT0();
        __syncthreads();
#pragma unroll
        for (int ks = 0; ks < 4; ks++) {
            uint32_t ah[2][4], al[2][4], bh[2][4], bl[2][4];
            int lr = lane & 15;
            int kh = lane >> 4;
            int chunk = ks * 2 + kh;
#pragma unroll
            for (int im = 0; im < 2; im++) {
                int row = wm * 32 + im * 16 + lr;
                uint32_t so = (uint32_t)(row * 128 + ((chunk ^ (row & 7)) << 4));
                LDMX4(ah[im][0], ah[im][1], ah[im][2], ah[im][3], sb + AH + so);
                LDMX4(al[im][0], al[im][1], al[im][2], al[im][3], sb + AL + so);
            }
#pragma unroll
            for (int in = 0; in < 2; in++) {
                int row = wn * 32 + in * 16 + lr;
                uint32_t so = (uint32_t)(row * 128 + ((chunk ^ (row & 7)) << 4));
                LDMX4(bh[in][0], bh[in][1], bh[in][2], bh[in][3], sb + BH + so);
                LDMX4(bl[in][0], bl[in][1], bl[in][2], bl[in][3], sb + BL + so);
            }
#pragma unroll
            for (int im = 0; im < 2; im++) {
#pragma unroll
                for (int in = 0; in < 2; in++) {
                    MMA16816(acc[im][2 * in],     ah[im], bh[in][0], bh[in][2]);
                    MMA16816(acc[im][2 * in + 1], ah[im], bh[in][1], bh[in][3]);
                    MMA16816(acc[im][2 * in],     ah[im], bl[in][0], bl[in][2]);
                    MMA16816(acc[im][2 * in + 1], ah[im], bl[in][1], bl[in][3]);
                    MMA16816(acc[im][2 * in],     al[im], bh[in][0], bh[in][2]);
                    MMA16816(acc[im][2 * in + 1], al[im], bh[in][1], bh[in][3]);
                }
            }
        }
    }
    int gid = lane >> 2, tig = lane & 3;
#pragma unroll
    for (int im = 0; im < 2; im++) {
        int m0 = bm + wm * 32 + im * 16 + gid;
#pragma unroll
        for (int s = 0; s < 4; s++) {
            int n = wn * 32 + s * 8 + tig * 2;
            float b0 = bext[n], b1 = bext[n + 1];
            if (m0 < NN) {
                float x = acc[im][s][0] + b0, y = acc[im][s][1] + b1;
                x = x > 0.f ? x : expm1f(x);
                y = y > 0.f ? y : expm1f(y);
                *(float2*)&g_x0[(size_t)m0 * 64 + n] = make_float2(x, y);
                *(__half2*)&g_x0h[(size_t)m0 * 64 + n] = __floats2half2_rn(x, y);
            }
            if (m0 + 8 < NN) {
                float x = acc[im][s][2] + b0, y = acc[im][s][3] + b1;
                x = x > 0.f ? x : expm1f(x);
                y = y > 0.f ? y : expm1f(y);
                *(float2*)&g_x0[(size_t)(m0 + 8) * 64 + n] = make_float2(x, y);
                *(__half2*)&g_x0h[(size_t)(m0 + 8) * 64 + n] = __floats2half2_rn(x, y);
            }
        }
    }
}

// ---------------- performer: kmax (row-major tile, f32x2) ----------------
__global__ __launch_bounds__(256) void kmax_kernel(const float* __restrict__ proj) {
    __shared__ float ks[32][132];
    __shared__ float proj_s[NBF * HDIM];
    int t = threadIdx.x;
    int row0 = blockIdx.x * 32;
    for (int i = t; i < NBF * HDIM; i += 256) proj_s[i] = proj[i];
    for (int i = t; i < 32 * 32; i += 256) {
        int r = i >> 5, c4 = i & 31;
        float4 v = make_float4(0.f, 0.f, 0.f, 0.f);
        if (row0 + r < NN) v = *(const float4*)&g_C1[(size_t)(row0 + r) * 512 + 128 + c4 * 4];
        *(float4*)&ks[r][c4 * 4] = v;
    }
    __syncthreads();
    int h = t >> 5, r = t & 31;
    float mx = -3e38f;
    if (row0 + r < NN) {
        ull k2[8];
#pragma unroll
        for (int d4 = 0; d4 < 4; d4++) {
            float4 v = *(const float4*)&ks[r][h * 16 + d4 * 4];
            k2[d4 * 2] = pack2(v.x * 0.5f, v.y * 0.5f);
            k2[d4 * 2 + 1] = pack2(v.z * 0.5f, v.w * 0.5f);
        }
#pragma unroll
        for (int m = 0; m < NBF; m++) {
            ull s2 = 0;
#pragma unroll
            for (int d4 = 0; d4 < 4; d4++) {
                float4 p = *(const float4*)&proj_s[m * 16 + d4 * 4];
                s2 = fma2(k2[d4 * 2], pack2(p.x, p.y), s2);
                s2 = fma2(k2[d4 * 2 + 1], pack2(p.z, p.w), s2);
            }
            float sx, sy;
            unpack2(s2, sx, sy);
            mx = fmaxf(mx, sx + sy);
        }
    }
#pragma unroll
    for (int o = 16; o > 0; o >>= 1) mx = fmaxf(mx, __shfl_xor_sync(0xffffffffu, mx, o));
    if (r == 0) atomicMaxFloat(&g_kmax[h], mx);
}

// ---------------- performer: kp (row-major tile, hoisted diag, f32x2) ----------
#define KPB 444
__global__ __launch_bounds__(352) void kp_acc_kernel(const float* __restrict__ proj) {
    __shared__ float s[32][264];
    __shared__ float diag_s[32][8];
    int t = threadIdx.x;
    int h = t / NBF, m = t - h * NBF;
    ull pm2[8];
#pragma unroll
    for (int d2 = 0; d2 < 8; d2++)
        pm2[d2] = pack2(proj[m * HDIM + d2 * 2], proj[m * HDIM + d2 * 2 + 1]);
    float kmaxh = g_kmax[h];
    const float ratio = rsqrtf((float)NBF);
    ull ctx2[8];
    float kc = 0.f;
#pragma unroll
    for (int d2 = 0; d2 < 8; d2++) ctx2[d2] = 0;

    for (int tile = blockIdx.x; tile < NTILES; tile += gridDim.x) {
        int row0 = tile * 32;
        __syncthreads();
        for (int i = t; i < 32 * 64; i += 352) {
            int r = i >> 6, c4 = i & 63;
            float4 v = make_float4(0.f, 0.f, 0.f, 0.f);
            if (row0 + r < NN) v = *(const float4*)&g_C1[(size_t)(row0 + r) * 512 + 128 + c4 * 4];
            *(float4*)&s[r][c4 * 4] = v;
        }
        __syncthreads();
        if (t < 256) {
            int rr = t >> 3, hh = t & 7;
            float sum = 0.f;
#pragma unroll
            for (int d4 = 0; d4 < 4; d4++) {
                float4 v = *(const float4*)&s[rr][hh * 16 + d4 * 4];
                sum += v.x * v.x + v.y * v.y + v.z * v.z + v.w * v.w;
            }
            diag_s[rr][hh] = 0.125f * sum;
        }
        __syncthreads();
        int rmax = min(32, NN - row0);
        for (int r = 0; r < rmax; r++) {
            ull d2 = 0;
#pragma unroll
            for (int d4 = 0; d4 < 4; d4++) {
                float4 v = *(const float4*)&s[r][h * 16 + d4 * 4];
                d2 = fma2(pack2(v.x, v.y), pm2[d4 * 2], d2);
                d2 = fma2(pack2(v.z, v.w), pm2[d4 * 2 + 1], d2);
            }
            float dx, dy;
            unpack2(d2, dx, dy);
            float kpv = ratio * (fexp(0.5f * (dx + dy) - diag_s[r][h] - kmaxh) + EPSV);
            kc += kpv;
            ull kpv2 = pack2(kpv, kpv);
#pragma unroll
            for (int d4 = 0; d4 < 4; d4++) {
                float4 v = *(const float4*)&s[r][128 + h * 16 + d4 * 4];
                ctx2[d4 * 2] = fma2(kpv2, pack2(v.x, v.y), ctx2[d4 * 2]);
                ctx2[d4 * 2 + 1] = fma2(kpv2, pack2(v.z, v.w), ctx2[d4 * 2 + 1]);
            }
        }
    }
    atomicAdd(&g_kcum[h * NBF + m], kc);
#pragma unroll
    for (int d2 = 0; d2 < 8; d2++) {
        float cx, cy;
        unpack2(ctx2[d2], cx, cy);
        atomicAdd(&g_ctx[(h * HDIM + d2 * 2) * NBF + m], cx);
        atomicAdd(&g_ctx[(h * HDIM + d2 * 2 + 1) * NBF + m], cy);
    }
}

// ---------------- attention (row-major q tile, ctx [h][m][d], f32x2) -----------
__global__ __launch_bounds__(256) void attn_kernel(const float* __restrict__ proj) {
    __shared__ float qs[32][132];
    __shared__ float proj_s[NBF * HDIM];
    __shared__ float kcum_s[NHEADS * NBF];
    __shared__ float ctxr[NHEADS][NBF * HDIM];
    int t = threadIdx.x;
    int row0 = blockIdx.x * 32;
    for (int i = t; i < NBF * HDIM; i += 256) proj_s[i] = proj[i];
    for (int i = t; i < NHEADS * NBF; i += 256) kcum_s[i] = g_kcum[i];
    for (int i = t; i < NHEADS * NBF * HDIM; i += 256) {
        int hh = i / (NBF * HDIM);
        int rem = i - hh * NBF * HDIM;
        int mm = rem >> 4, dd = rem & 15;
        ctxr[hh][mm * 16 + dd] = g_ctx[(hh * HDIM + dd) * NBF + mm];
    }
    for (int i = t; i < 32 * 32; i += 256) {
        int r = i >> 5, c4 = i & 31;
        float4 v = make_float4(0.f, 0.f, 0.f, 0.f);
        if (row0 + r < NN) v = *(const float4*)&g_C1[(size_t)(row0 + r) * 512 + c4 * 4];
        *(float4*)&qs[r][c4 * 4] = v;
    }
    for (int i = t; i < 32 * 64; i += 256) {
        int r = i >> 6, dp = (i & 63) * 2;
        if (row0 + r < NN) {
            float2 v = *(const float2*)&g_C1[(size_t)(row0 + r) * 512 + 384 + dp];
            v.x = v.x > 0.f ? v.x : expm1f(v.x);
            v.y = v.y > 0.f ? v.y : expm1f(v.y);
            __nv_bfloat16 hx = __float2bfloat16(v.x), hy = __float2bfloat16(v.y);
            size_t idx = (size_t)(row0 + r) * 256 + dp;
            *(__nv_bfloat162*)&g_h_hi[idx] = __nv_bfloat162(hx, hy);
            *(__nv_bfloat162*)&g_h_lo[idx] =
                __nv_bfloat162(__float2bfloat16(v.x - __bfloat162float(hx)),
                               __float2bfloat16(v.y - __bfloat162float(hy)));
        }
    }
    __syncthreads();
    int h = t >> 5, r = t & 31;
    if (row0 + r >= NN) return;
    ull q2[8];
    float diag = 0.f;
#pragma unroll
    for (int d4 = 0; d4 < 4; d4++) {
        float4 v = *(const float4*)&qs[r][h * 16 + d4 * 4];
        float a = v.x * 0.5f, b = v.y * 0.5f, c = v.z * 0.5f, d = v.w * 0.5f;
        q2[d4 * 2] = pack2(a, b);
        q2[d4 * 2 + 1] = pack2(c, d);
        diag += a * a + b * b + c * c + d * d;
    }
    diag *= 0.5f;
    float dash[NBF];
    float qmax = -3e38f;
#pragma unroll
    for (int m = 0; m < NBF; m++) {
        ull s2 = 0;
#pragma unroll
        for (int d4 = 0; d4 < 4; d4++) {
            float4 p = *(const float4*)&proj_s[m * 16 + d4 * 4];
            s2 = fma2(q2[d4 * 2], pack2(p.x, p.y), s2);
            s2 = fma2(q2[d4 * 2 + 1], pack2(p.z, p.w), s2);
        }
        float sx, sy;
        unpack2(s2, sx, sy);
        dash[m] = sx + sy;
        qmax = fmaxf(qmax, dash[m]);
    }
    float den = 0.f;
    ull outv2[8];
#pragma unroll
    for (int d2 = 0; d2 < 8; d2++) outv2[d2] = 0;
    const float ratio = rsqrtf((float)NBF);
#pragma unroll
    for (int m = 0; m < NBF; m++) {
        float qp = ratio * (fexp(dash[m] - diag - qmax) + EPSV);
        den += qp * kcum_s[h * NBF + m];
        ull qp2 = pack2(qp, qp);
#pragma unroll
        for (int d4 = 0; d4 < 4; d4++) {
            float4 cv = *(const float4*)&ctxr[h][m * 16 + d4 * 4];
            outv2[d4 * 2] = fma2(qp2, pack2(cv.x, cv.y), outv2[d4 * 2]);
            outv2[d4 * 2 + 1] = fma2(qp2, pack2(cv.z, cv.w), outv2[d4 * 2 + 1]);
        }
    }
    float dinv = 1.f / den;
    size_t hbase = (size_t)(row0 + r) * 256 + HIDDIM + h * HDIM;
#pragma unroll
    for (int d2 = 0; d2 < 8; d2++) {
        float x, y;
        unpack2(outv2[d2], x, y);
        x *= dinv; y *= dinv;
        x = x > 0.f ? x : expm1f(x);
        y = y > 0.f ? y : expm1f(y);
        __nv_bfloat16 hx = __float2bfloat16(x), hy = __float2bfloat16(y);
        *(__nv_bfloat162*)&g_h_hi[hbase + d2 * 2] = __nv_bfloat162(hx, hy);
        *(__nv_bfloat162*)&g_h_lo[hbase + d2 * 2] =
            __nv_bfloat162(__float2bfloat16(x - __bfloat162float(hx)),
                           __float2bfloat16(y - __bfloat162float(hy)));
    }
}

// ---------------- APPNP graph prep ----------------
__global__ void deg_kernel(const int* __restrict__ col) {
    int e = blockIdx.x * blockDim.x + threadIdx.x;
    if (e < NEDGE) atomicAdd(&g_cnt[col[e]], 1);
}

__global__ __launch_bounds__(1024) void scan_kernel() {
    __shared__ int wsum[32];
    __shared__ int carry_s;
    int t = threadIdx.x;
    int lane = t & 31, wid = t >> 5;
    if (t == 0) carry_s = 0;
    __syncthreads();
    for (int base = 0; base < NN; base += 1024) {
        int i = base + t;
        int v = (i < NN) ? g_cnt[i] : 0;
        int x = v;
#pragma unroll
        for (int o = 1; o < 32; o <<= 1) {
            int y = __shfl_up_sync(0xffffffffu, x, o);
            if (lane >= o) x += y;
        }
        if (lane == 31) wsum[wid] = x;
        __syncthreads();
        if (wid == 0) {
            int s = wsum[lane];
#pragma unroll
            for (int o = 1; o < 32; o <<= 1) {
                int y = __shfl_up_sync(0xffffffffu, s, o);
                if (lane >= o) s += y;
            }
            wsum[lane] = s;
        }
        __syncthreads();
        int incl = x + (wid > 0 ? wsum[wid - 1] : 0);
        int carry = carry_s;
        if (i < NN) {
            int off = carry + incl - v;
            g_off[i] = off;
            g_cursor[i] = off;
            g_dis[i] = rsqrtf((float)(v + 1));
        }
        __syncthreads();
        if (t == 1023) carry_s = carry + incl;
        __syncthreads();
    }
    if (t == 0) g_off[NN] = carry_s;
}

__global__ void fill_kernel(const int* __restrict__ row, const int* __restrict__ col) {
    int e = blockIdx.x * blockDim.x + threadIdx.x;
    if (e >= NEDGE) return;
    int r = row[e], cl = col[e];
    int pos = atomicAdd(&g_cursor[cl], 1);
    g_csr[pos] = make_int2(r, __float_as_int(g_dis[r] * g_dis[cl]));
}

// ---------------- APPNP hop: 2 nodes per warp (16 lanes each), 16-deep MLP --------
template <bool LAST>
__global__ __launch_bounds__(256) void hop_kernel(int stage, float* __restrict__ out,
                                                  int out_size) {
    int gwarp = blockIdx.x * 8 + (threadIdx.x >> 5);
    int lane = threadIdx.x & 31;
    int sub = lane >> 4, li = lane & 15;
    int node = gwarp * 2 + sub;          // NN even; all nodes covered
    bool valid = node < NN;
    const __half* src = (stage == 0) ? g_x0h : ((stage & 1) ? g_ha : g_hb);
    __half* dst = (stage & 1) ? g_hb : g_ha;
    int s = 0, e = 0;
    if (valid) { s = g_off[node]; e = g_off[node + 1]; }
    int deg = e - s;
    int mdeg = deg;
#pragma unroll
    for (int o = 16; o > 0; o >>= 1) mdeg = max(mdeg, __shfl_xor_sync(0xffffffffu, mdeg, o));
    float di = valid ? g_dis[node] : 0.f;
    float4 x0v = make_float4(0.f, 0.f, 0.f, 0.f);
    float a0, a1, a2, a3;
    {
        uint2 sv = make_uint2(0u, 0u);
        if (valid) {
            x0v = *(const float4*)&g_x0[(size_t)node * 64 + li * 4];
            sv = *(const uint2*)&src[(size_t)node * 64 + li * 4];
        }
        float2 p0 = __half22float2(*(__half2*)&sv.x);
        float2 p1 = __half22float2(*(__half2*)&sv.y);
        float dd = di * di;
        a0 = dd * p0.x; a1 = dd * p0.y; a2 = dd * p1.x; a3 = dd * p1.y;
    }
    for (int jj = 0; jj < mdeg; jj += 8) {
        int2 ce[8];
#pragma unroll
        for (int u = 0; u < 8; u++)
            ce[u] = (jj + u < deg) ? g_csr[s + jj + u] : make_int2(0, 0);
#pragma unroll
        for (int u = 0; u < 8; u++) {
            if (jj + u < deg) {
                float wt = __int_as_float(ce[u].y);
                uint2 v = *(const uint2*)&src[(size_t)ce[u].x * 64 + li * 4];
                float2 p0 = __half22float2(*(__half2*)&v.x);
                float2 p1 = __half22float2(*(__half2*)&v.y);
                a0 += wt * p0.x; a1 += wt * p0.y; a2 += wt * p1.x; a3 += wt * p1.y;
            }
        }
    }
    float r0 = (1.f - ALPHAV) * a0 + ALPHAV * x0v.x;
    float r1 = (1.f - ALPHAV) * a1 + ALPHAV * x0v.y;
    float r2 = (1.f - ALPHAV) * a2 + ALPHAV * x0v.z;
    float r3 = (1.f - ALPHAV) * a3 + ALPHAV * x0v.w;
    if (!valid) return;
    if (!LAST) {
        uint2 o2;
        *(__half2*)&o2.x = __floats2half2_rn(r0, r1);
        *(__half2*)&o2.y = __floats2half2_rn(r2, r3);
        *(uint2*)&dst[(size_t)node * 64 + li * 4] = o2;
    } else {
        float mx = fmaxf(fmaxf(r0, r1), fmaxf(r2, r3));
#pragma unroll
        for (int o = 8; o > 0; o >>= 1) mx = fmaxf(mx, __shfl_xor_sync(0xffffffffu, mx, o));
        float ss = __expf(r0 - mx) + __expf(r1 - mx) + __expf(r2 - mx) + __expf(r3 - mx);
#pragma unroll
        for (int o = 8; o > 0; o >>= 1) ss += __shfl_xor_sync(0xffffffffu, ss, o);
        float lse = mx + logf(ss);
        int i0 = node * 64 + li * 4;
        if (i0 + 3 < out_size)
            *(float4*)&out[i0] = make_float4(r0 - lse, r1 - lse, r2 - lse, r3 - lse);
        int j0 = NN * 64 + i0;
        if (j0 + 3 < out_size)
            *(float4*)&out[j0] = make_float4(r0, r1, r2, r3);
    }
}

// ---------------- launch ----------------
extern "C" void kernel_launch(void* const* d_in, const int* in_sizes, int n_in,
                              void* d_out, int out_size) {
    if (n_in < 13) return;
    const float* data = (const float*)d_in[0];
    const int* ei = (const int*)d_in[1];
    const float* l1w = (const float*)d_in[2];
    const float* l1b = (const float*)d_in[3];
    const float* l2w = (const float*)d_in[4];
    const float* l2b = (const float*)d_in[5];
    const float* qw = (const float*)d_in[6];
    const float* qb = (const float*)d_in[7];
    const float* kw = (const float*)d_in[8];
    const float* kb = (const float*)d_in[9];
    const float* vw = (const float*)d_in[10];
    const float* vb = (const float*)d_in[11];
    const float* proj = (const float*)d_in[12];
    const int* row = ei;
    const int* col = ei + NEDGE;

    cudaFuncSetAttribute(hmma_gemm_kernel, cudaFuncAttributeMaxDynamicSharedMemorySize, HG_SMEM);
    cudaFuncSetAttribute(gemm2_kernel, cudaFuncAttributeMaxDynamicSharedMemorySize, G2_SMEM);

    prep_kernel<<<1024, 256>>>(data, qw, kw, vw, l1w, qb, kb, vb, l1b, l2w);

    dim3 g1((NN + 127) / 128, 4);
    hmma_gemm_kernel<<<g1, 256, HG_SMEM>>>();

    kmax_kernel<<<NTILES, 256>>>(proj);
    kp_acc_kernel<<<KPB, 352>>>(proj);
    attn_kernel<<<NTILES, 256>>>(proj);

    gemm2_kernel<<<(NN + 127) / 128, 256, G2_SMEM>>>(l2b);

    deg_kernel<<<(NEDGE + 255) / 256, 256>>>(col);
    scan_kernel<<<1, 1024>>>();
    fill_kernel<<<(NEDGE + 255) / 256, 256>>>(row, col);

    // 2 nodes per warp, 16 nodes per block
    int hop_grid = (NN + 15) / 16;
    for (int k = 0; k < 9; k++)
        hop_kernel<false><<<hop_grid, 256>>>(k, nullptr, 0);
    hop_kernel<true><<<hop_grid, 256>>>(9, (float*)d_out, out_size);
}

// round 14
// speedup vs baseline: 1.2289x; 1.0805x over previous
#include <cuda_runtime.h>
#include <cuda_bf16.h>
#include <cuda_fp16.h>
#include <math.h>
#include <stdint.h>

// ---------------- problem constants ----------------
#define NN     50000
#define FIN    256
#define HIDDIM 128
#define NHEADS 8
#define HDIM   16
#define NCLS   64
#define NEDGE  1250000
#define NBF    44
#define EPSV   1e-4f
#define ALPHAV 0.1f

#define NTILES ((NN + 31) / 32)

// ---------------- scratch (device globals; no runtime alloc) ----------------
__device__ float g_bias1[512];
__device__ __nv_bfloat16 g_Bt_hi[512 * 256];
__device__ __nv_bfloat16 g_Bt_lo[512 * 256];
__device__ __nv_bfloat16 g_B2_hi[64 * 256];
__device__ __nv_bfloat16 g_B2_lo[64 * 256];
__device__ __nv_bfloat16 g_A_hi[(size_t)NN * 256];
__device__ __nv_bfloat16 g_A_lo[(size_t)NN * 256];
__device__ float g_C1[(size_t)NN * 512];
__device__ float g_kmax[NHEADS];
__device__ float g_kcum[NHEADS * NBF];
__device__ float g_ctx[NHEADS * HDIM * NBF];   // [h][d][m]
__device__ __nv_bfloat16 g_h_hi[(size_t)NN * 256];
__device__ __nv_bfloat16 g_h_lo[(size_t)NN * 256];
__device__ float  g_x0[(size_t)NN * NCLS];
__device__ __half g_x0h[(size_t)NN * NCLS];
__device__ __half g_ha[(size_t)NN * NCLS];
__device__ __half g_hb[(size_t)NN * NCLS];
__device__ int   g_cnt[NN];
__device__ int   g_off[NN + 1];
__device__ int   g_cursor[NN];
__device__ float g_dis[NN];
__device__ int2  g_csr[NEDGE];

// ---------------- PTX helpers ----------------
__device__ __forceinline__ uint32_t smem_u32(const void* p) {
    uint32_t a;
    asm("{ .reg .u64 t; cvta.to.shared.u64 t, %1; cvt.u32.u64 %0, t; }" : "=r"(a) : "l"(p));
    return a;
}
#define LDMX4(r0, r1, r2, r3, addr)                                          \
    asm volatile("ldmatrix.sync.aligned.m8n8.x4.shared.b16 {%0,%1,%2,%3}, [%4];" \
                 : "=r"(r0), "=r"(r1), "=r"(r2), "=r"(r3) : "r"(addr))
#define MMA16816(c, a, b0v, b1v)                                             \
    asm volatile("mma.sync.aligned.m16n8k16.row.col.f32.bf16.bf16.f32 "      \
                 "{%0,%1,%2,%3},{%4,%5,%6,%7},{%8,%9},{%0,%1,%2,%3};"        \
                 : "+f"((c)[0]), "+f"((c)[1]), "+f"((c)[2]), "+f"((c)[3])    \
                 : "r"((a)[0]), "r"((a)[1]), "r"((a)[2]), "r"((a)[3]),       \
                   "r"(b0v), "r"(b1v))
__device__ __forceinline__ void cp_async16(uint32_t saddr, const void* gaddr, uint32_t srcsize) {
    asm volatile("cp.async.cg.shared.global [%0], [%1], 16, %2;"
                 :: "r"(saddr), "l"(gaddr), "r"(srcsize) : "memory");
}
#define CP_COMMIT() asm volatile("cp.async.commit_group;" ::: "memory")
#define CP_WAIT0()  asm volatile("cp.async.wait_group 0;" ::: "memory")

// ---------------- packed f32x2 helpers (FFMA2 on sm_103a) ----------------
typedef unsigned long long ull;
__device__ __forceinline__ ull pack2(float x, float y) {
    ull r; asm("mov.b64 %0, {%1, %2};" : "=l"(r) : "f"(x), "f"(y)); return r;
}
__device__ __forceinline__ void unpack2(ull v, float& x, float& y) {
    asm("mov.b64 {%0, %1}, %2;" : "=f"(x), "=f"(y) : "l"(v));
}
__device__ __forceinline__ ull fma2(ull a, ull b, ull c) {
    ull r; asm("fma.rn.f32x2 %0, %1, %2, %3;" : "=l"(r) : "l"(a), "l"(b), "l"(c)); return r;
}

// ---------------- misc helpers ----------------
__device__ __forceinline__ void atomicMaxFloat(float* addr, float val) {
    int* ia = (int*)addr;
    int old = *ia;
    while (__int_as_float(old) < val) {
        int assumed = old;
        old = atomicCAS(ia, assumed, __float_as_int(val));
        if (old == assumed) break;
    }
}

__device__ __forceinline__ float fexp(float x) {
    float y = fmaxf(x * 1.44269504f, -125.0f);
    float z = y + 12582912.0f;
    int   n = __float_as_int(z) - 0x4B400000;
    float f = y - (z - 12582912.0f);
    float q = 0.00133335581f;
    q = q * f + 0.00961812911f;
    q = q * f + 0.0555041087f;
    q = q * f + 0.240226507f;
    q = q * f + 0.693147181f;
    q = q * f + 1.0f;
    return q * __int_as_float((n + 127) << 23);
}

// ---------------- prep: pack weights + split data + init (fused) ----------------
__global__ __launch_bounds__(256) void prep_kernel(
    const float* __restrict__ data,
    const float* __restrict__ qw, const float* __restrict__ kw,
    const float* __restrict__ vw, const float* __restrict__ l1w,
    const float* __restrict__ qb, const float* __restrict__ kb,
    const float* __restrict__ vb, const float* __restrict__ l1b,
    const float* __restrict__ l2w) {
    int gt = blockIdx.x * 256 + threadIdx.x;
    int NT = gridDim.x * 256;
    if (gt < NHEADS) g_kmax[gt] = -3e38f;
    for (int i = gt; i < NHEADS * NBF; i += NT) g_kcum[i] = 0.f;
    for (int i = gt; i < NHEADS * HDIM * NBF; i += NT) g_ctx[i] = 0.f;
    for (int i = gt; i < NN; i += NT) g_cnt[i] = 0;
    for (int i = gt; i < 512 * 256; i += NT) {
        int n = i >> 8, k = i & 255;
        const float* src = (n < 128) ? qw : (n < 256) ? kw : (n < 384) ? vw : l1w;
        float w = src[k * 128 + (n & 127)];
        __nv_bfloat16 hi = __float2bfloat16(w);
        g_Bt_hi[i] = hi;
        g_Bt_lo[i] = __float2bfloat16(w - __bfloat162float(hi));
    }
    if (gt < 512) {
        const float* sb = (gt < 128) ? qb : (gt < 256) ? kb : (gt < 384) ? vb : l1b;
        g_bias1[gt] = sb[gt & 127];
    }
    for (int i = gt; i < 64 * 256; i += NT) {
        int n = i >> 8, k = i & 255;
        float w = l2w[k * 64 + n];
        __nv_bfloat16 hi = __float2bfloat16(w);
        g_B2_hi[i] = hi;
        g_B2_lo[i] = __float2bfloat16(w - __bfloat162float(hi));
    }
    for (int i4 = gt; i4 < NN * 64; i4 += NT) {
        size_t base = (size_t)i4 * 4;
        float4 v = *(const float4*)&data[base];
        __nv_bfloat16 h0 = __float2bfloat16(v.x), h1 = __float2bfloat16(v.y);
        __nv_bfloat16 h2 = __float2bfloat16(v.z), h3 = __float2bfloat16(v.w);
        __nv_bfloat162* ph = (__nv_bfloat162*)&g_A_hi[base];
        ph[0] = __nv_bfloat162(h0, h1);
        ph[1] = __nv_bfloat162(h2, h3);
        __nv_bfloat162* pl = (__nv_bfloat162*)&g_A_lo[base];
        pl[0] = __nv_bfloat162(__float2bfloat16(v.x - __bfloat162float(h0)),
                               __float2bfloat16(v.y - __bfloat162float(h1)));
        pl[1] = __nv_bfloat162(__float2bfloat16(v.z - __bfloat162float(h2)),
                               __float2bfloat16(v.w - __bfloat162float(h3)));
    }
}

// ---------------- HMMA split-bf16 GEMM1 ----------------
#define HG_SMEM 65536
__global__ __launch_bounds__(256) void hmma_gemm_kernel() {
    extern __shared__ char smem[];
    const uint32_t sb = smem_u32(smem);
    const int t = threadIdx.x;
    const int w = t >> 5;
    const int lane = t & 31;
    const int wm = w >> 1, wn = w & 1;
    const int bm = blockIdx.x * 128;
    const int bn = blockIdx.y * 128;
    const uint32_t AH = 0, AL = 16384, BH = 32768, BL = 49152;

    float acc[2][8][4];
#pragma unroll
    for (int i = 0; i < 2; i++)
#pragma unroll
        for (int j = 0; j < 8; j++)
#pragma unroll
            for (int k = 0; k < 4; k++) acc[i][j][k] = 0.f;

    const int srow = t >> 3;
    const int schk = t & 7;

    for (int c = 0; c < 4; c++) {
        const int k0 = c * 64;
        if (c) __syncthreads();
#pragma unroll
        for (int rep = 0; rep < 4; rep++) {
            int row = rep * 32 + srow;
            uint32_t so = (uint32_t)(row * 128 + ((schk ^ (row & 7)) << 4));
            bool in = (bm + row) < NN;
            uint32_t asz = in ? 16u : 0u;
            size_t ga = (size_t)(in ? (bm + row) : 0) * 256 + k0 + schk * 8;
            cp_async16(sb + AH + so, &g_A_hi[ga], asz);
            cp_async16(sb + AL + so, &g_A_lo[ga], asz);
            size_t gb = (size_t)(bn + row) * 256 + k0 + schk * 8;
            cp_async16(sb + BH + so, &g_Bt_hi[gb], 16u);
            cp_async16(sb + BL + so, &g_Bt_lo[gb], 16u);
        }
        CP_COMMIT();
        CP_WAIT0();
        __syncthreads();

#pragma unroll
        for (int ks = 0; ks < 4; ks++) {
            uint32_t ah[2][4], al[2][4], bh[4][4], bl[4][4];
            int lr = lane & 15;
            int kh = lane >> 4;
            int chunk = ks * 2 + kh;
#pragma unroll
            for (int im = 0; im < 2; im++) {
                int row = wm * 32 + im * 16 + lr;
                uint32_t so = (uint32_t)(row * 128 + ((chunk ^ (row & 7)) << 4));
                LDMX4(ah[im][0], ah[im][1], ah[im][2], ah[im][3], sb + AH + so);
                LDMX4(al[im][0], al[im][1], al[im][2], al[im][3], sb + AL + so);
            }
#pragma unroll
            for (int in = 0; in < 4; in++) {
                int row = wn * 64 + in * 16 + lr;
                uint32_t so = (uint32_t)(row * 128 + ((chunk ^ (row & 7)) << 4));
                LDMX4(bh[in][0], bh[in][1], bh[in][2], bh[in][3], sb + BH + so);
                LDMX4(bl[in][0], bl[in][1], bl[in][2], bl[in][3], sb + BL + so);
            }
#pragma unroll
            for (int im = 0; im < 2; im++) {
#pragma unroll
                for (int in = 0; in < 4; in++) {
                    MMA16816(acc[im][2 * in],     ah[im], bh[in][0], bh[in][2]);
                    MMA16816(acc[im][2 * in + 1], ah[im], bh[in][1], bh[in][3]);
                    MMA16816(acc[im][2 * in],     ah[im], bl[in][0], bl[in][2]);
                    MMA16816(acc[im][2 * in + 1], ah[im], bl[in][1], bl[in][3]);
                    MMA16816(acc[im][2 * in],     al[im], bh[in][0], bh[in][2]);
                    MMA16816(acc[im][2 * in + 1], al[im], bh[in][1], bh[in][3]);
                }
            }
        }
    }
    int gid = lane >> 2, tig = lane & 3;
#pragma unroll
    for (int im = 0; im < 2; im++) {
        int m0 = bm + wm * 32 + im * 16 + gid;
#pragma unroll
        for (int s = 0; s < 8; s++) {
            int n = bn + wn * 64 + s * 8 + tig * 2;
            float b0 = g_bias1[n], b1 = g_bias1[n + 1];
            if (m0 < NN) {
                float2 v = make_float2(acc[im][s][0] + b0, acc[im][s][1] + b1);
                *(float2*)&g_C1[(size_t)m0 * 512 + n] = v;
            }
            if (m0 + 8 < NN) {
                float2 v = make_float2(acc[im][s][2] + b0, acc[im][s][3] + b1);
                *(float2*)&g_C1[(size_t)(m0 + 8) * 512 + n] = v;
            }
        }
    }
}

// ---------------- HMMA split-bf16 GEMM2 ----------------
#define G2_SMEM (16384 * 2 + 16384)
__global__ __launch_bounds__(256) void gemm2_kernel(const float* __restrict__ bext) {
    extern __shared__ char smem[];
    const uint32_t sb = smem_u32(smem);
    const int t = threadIdx.x;
    const int w = t >> 5;
    const int lane = t & 31;
    const int wm = w >> 1, wn = w & 1;
    const int bm = blockIdx.x * 128;
    const uint32_t AH = 0, AL = 16384, BH = 32768, BL = 40960;

    float acc[2][4][4];
#pragma unroll
    for (int i = 0; i < 2; i++)
#pragma unroll
        for (int j = 0; j < 4; j++)
#pragma unroll
            for (int k = 0; k < 4; k++) acc[i][j][k] = 0.f;

    const int srow = t >> 3;
    const int schk = t & 7;

    for (int c = 0; c < 4; c++) {
        const int k0 = c * 64;
        if (c) __syncthreads();
#pragma unroll
        for (int rep = 0; rep < 4; rep++) {
            int row = rep * 32 + srow;
            uint32_t so = (uint32_t)(row * 128 + ((schk ^ (row & 7)) << 4));
            bool in = (bm + row) < NN;
            uint32_t asz = in ? 16u : 0u;
            size_t ga = (size_t)(in ? (bm + row) : 0) * 256 + k0 + schk * 8;
            cp_async16(sb + AH + so, &g_h_hi[ga], asz);
            cp_async16(sb + AL + so, &g_h_lo[ga], asz);
        }
#pragma unroll
        for (int rep = 0; rep < 2; rep++) {
            int row = rep * 32 + srow;
            uint32_t so = (uint32_t)(row * 128 + ((schk ^ (row & 7)) << 4));
            size_t gb = (size_t)row * 256 + k0 + schk * 8;
            cp_async16(sb + BH + so, &g_B2_hi[gb], 16u);
            cp_async16(sb + BL + so, &g_B2_lo[gb], 16u);
        }
        CP_COMMIT();
        CP_WAIT0();
        __syncthreads();
#pragma unroll
        for (int ks = 0; ks < 4; ks++) {
            uint32_t ah[2][4], al[2][4], bh[2][4], bl[2][4];
            int lr = lane & 15;
            int kh = lane >> 4;
            int chunk = ks * 2 + kh;
#pragma unroll
            for (int im = 0; im < 2; im++) {
                int row = wm * 32 + im * 16 + lr;
                uint32_t so = (uint32_t)(row * 128 + ((chunk ^ (row & 7)) << 4));
                LDMX4(ah[im][0], ah[im][1], ah[im][2], ah[im][3], sb + AH + so);
                LDMX4(al[im][0], al[im][1], al[im][2], al[im][3], sb + AL + so);
            }
#pragma unroll
            for (int in = 0; in < 2; in++) {
                int row = wn * 32 + in * 16 + lr;
                uint32_t so = (uint32_t)(row * 128 + ((chunk ^ (row & 7)) << 4));
                LDMX4(bh[in][0], bh[in][1], bh[in][2], bh[in][3], sb + BH + so);
                LDMX4(bl[in][0], bl[in][1], bl[in][2], bl[in][3], sb + BL + so);
            }
#pragma unroll
            for (int im = 0; im < 2; im++) {
#pragma unroll
                for (int in = 0; in < 2; in++) {
                    MMA16816(acc[im][2 * in],     ah[im], bh[in][0], bh[in][2]);
                    MMA16816(acc[im][2 * in + 1], ah[im], bh[in][1], bh[in][3]);
                    MMA16816(acc[im][2 * in],     ah[im], bl[in][0], bl[in][2]);
                    MMA16816(acc[im][2 * in + 1], ah[im], bl[in][1], bl[in][3]);
                    MMA16816(acc[im][2 * in],     al[im], bh[in][0], bh[in][2]);
                    MMA16816(acc[im][2 * in + 1], al[im], bh[in][1], bh[in][3]);
                }
            }
        }
    }
    int gid = lane >> 2, tig = lane & 3;
#pragma unroll
    for (int im = 0; im < 2; im++) {
        int m0 = bm + wm * 32 + im * 16 + gid;
#pragma unroll
        for (int s = 0; s < 4; s++) {
            int n = wn * 32 + s * 8 + tig * 2;
            float b0 = bext[n], b1 = bext[n + 1];
            if (m0 < NN) {
                float x = acc[im][s][0] + b0, y = acc[im][s][1] + b1;
                x = x > 0.f ? x : expm1f(x);
                y = y > 0.f ? y : expm1f(y);
                *(float2*)&g_x0[(size_t)m0 * 64 + n] = make_float2(x, y);
                *(__half2*)&g_x0h[(size_t)m0 * 64 + n] = __floats2half2_rn(x, y);
            }
            if (m0 + 8 < NN) {
                float x = acc[im][s][2] + b0, y = acc[im][s][3] + b1;
                x = x > 0.f ? x : expm1f(x);
                y = y > 0.f ? y : expm1f(y);
                *(float2*)&g_x0[(size_t)(m0 + 8) * 64 + n] = make_float2(x, y);
                *(__half2*)&g_x0h[(size_t)(m0 + 8) * 64 + n] = __floats2half2_rn(x, y);
            }
        }
    }
}

// ---------------- performer: kmax (row-major tile, f32x2) ----------------
__global__ __launch_bounds__(256) void kmax_kernel(const float* __restrict__ proj) {
    __shared__ float ks[32][132];
    __shared__ float proj_s[NBF * HDIM];
    int t = threadIdx.x;
    int row0 = blockIdx.x * 32;
    for (int i = t; i < NBF * HDIM; i += 256) proj_s[i] = proj[i];
    for (int i = t; i < 32 * 32; i += 256) {
        int r = i >> 5, c4 = i & 31;
        float4 v = make_float4(0.f, 0.f, 0.f, 0.f);
        if (row0 + r < NN) v = *(const float4*)&g_C1[(size_t)(row0 + r) * 512 + 128 + c4 * 4];
        *(float4*)&ks[r][c4 * 4] = v;
    }
    __syncthreads();
    int h = t >> 5, r = t & 31;
    float mx = -3e38f;
    if (row0 + r < NN) {
        ull k2[8];
#pragma unroll
        for (int d4 = 0; d4 < 4; d4++) {
            float4 v = *(const float4*)&ks[r][h * 16 + d4 * 4];
            k2[d4 * 2] = pack2(v.x * 0.5f, v.y * 0.5f);
            k2[d4 * 2 + 1] = pack2(v.z * 0.5f, v.w * 0.5f);
        }
#pragma unroll
        for (int m = 0; m < NBF; m++) {
            ull s2 = 0;
#pragma unroll
            for (int d4 = 0; d4 < 4; d4++) {
                float4 p = *(const float4*)&proj_s[m * 16 + d4 * 4];
                s2 = fma2(k2[d4 * 2], pack2(p.x, p.y), s2);
                s2 = fma2(k2[d4 * 2 + 1], pack2(p.z, p.w), s2);
            }
            float sx, sy;
            unpack2(s2, sx, sy);
            mx = fmaxf(mx, sx + sy);
        }
    }
#pragma unroll
    for (int o = 16; o > 0; o >>= 1) mx = fmaxf(mx, __shfl_xor_sync(0xffffffffu, mx, o));
    if (r == 0) atomicMaxFloat(&g_kmax[h], mx);
}

// ---------------- performer: kp (row-major tile, hoisted diag, f32x2) ----------
#define KPB 444
__global__ __launch_bounds__(352) void kp_acc_kernel(const float* __restrict__ proj) {
    __shared__ float s[32][264];
    __shared__ float diag_s[32][8];
    int t = threadIdx.x;
    int h = t / NBF, m = t - h * NBF;
    ull pm2[8];
#pragma unroll
    for (int d2 = 0; d2 < 8; d2++)
        pm2[d2] = pack2(proj[m * HDIM + d2 * 2], proj[m * HDIM + d2 * 2 + 1]);
    float kmaxh = g_kmax[h];
    const float ratio = rsqrtf((float)NBF);
    ull ctx2[8];
    float kc = 0.f;
#pragma unroll
    for (int d2 = 0; d2 < 8; d2++) ctx2[d2] = 0;

    for (int tile = blockIdx.x; tile < NTILES; tile += gridDim.x) {
        int row0 = tile * 32;
        __syncthreads();
        for (int i = t; i < 32 * 64; i += 352) {
            int r = i >> 6, c4 = i & 63;
            float4 v = make_float4(0.f, 0.f, 0.f, 0.f);
            if (row0 + r < NN) v = *(const float4*)&g_C1[(size_t)(row0 + r) * 512 + 128 + c4 * 4];
            *(float4*)&s[r][c4 * 4] = v;
        }
        __syncthreads();
        if (t < 256) {
            int rr = t >> 3, hh = t & 7;
            float sum = 0.f;
#pragma unroll
            for (int d4 = 0; d4 < 4; d4++) {
                float4 v = *(const float4*)&s[rr][hh * 16 + d4 * 4];
                sum += v.x * v.x + v.y * v.y + v.z * v.z + v.w * v.w;
            }
            diag_s[rr][hh] = 0.125f * sum;
        }
        __syncthreads();
        int rmax = min(32, NN - row0);
        for (int r = 0; r < rmax; r++) {
            ull d2 = 0;
#pragma unroll
            for (int d4 = 0; d4 < 4; d4++) {
                float4 v = *(const float4*)&s[r][h * 16 + d4 * 4];
                d2 = fma2(pack2(v.x, v.y), pm2[d4 * 2], d2);
                d2 = fma2(pack2(v.z, v.w), pm2[d4 * 2 + 1], d2);
            }
            float dx, dy;
            unpack2(d2, dx, dy);
            float kpv = ratio * (fexp(0.5f * (dx + dy) - diag_s[r][h] - kmaxh) + EPSV);
            kc += kpv;
            ull kpv2 = pack2(kpv, kpv);
#pragma unroll
            for (int d4 = 0; d4 < 4; d4++) {
                float4 v = *(const float4*)&s[r][128 + h * 16 + d4 * 4];
                ctx2[d4 * 2] = fma2(kpv2, pack2(v.x, v.y), ctx2[d4 * 2]);
                ctx2[d4 * 2 + 1] = fma2(kpv2, pack2(v.z, v.w), ctx2[d4 * 2 + 1]);
            }
        }
    }
    atomicAdd(&g_kcum[h * NBF + m], kc);
#pragma unroll
    for (int d2 = 0; d2 < 8; d2++) {
        float cx, cy;
        unpack2(ctx2[d2], cx, cy);
        atomicAdd(&g_ctx[(h * HDIM + d2 * 2) * NBF + m], cx);
        atomicAdd(&g_ctx[(h * HDIM + d2 * 2 + 1) * NBF + m], cy);
    }
}

// ---------------- attention (row-major q tile, ctx [h][m][d], f32x2) -----------
__global__ __launch_bounds__(256) void attn_kernel(const float* __restrict__ proj) {
    __shared__ float qs[32][132];
    __shared__ float proj_s[NBF * HDIM];
    __shared__ float kcum_s[NHEADS * NBF];
    __shared__ float ctxr[NHEADS][NBF * HDIM];
    int t = threadIdx.x;
    int row0 = blockIdx.x * 32;
    for (int i = t; i < NBF * HDIM; i += 256) proj_s[i] = proj[i];
    for (int i = t; i < NHEADS * NBF; i += 256) kcum_s[i] = g_kcum[i];
    for (int i = t; i < NHEADS * NBF * HDIM; i += 256) {
        int hh = i / (NBF * HDIM);
        int rem = i - hh * NBF * HDIM;
        int mm = rem >> 4, dd = rem & 15;
        ctxr[hh][mm * 16 + dd] = g_ctx[(hh * HDIM + dd) * NBF + mm];
    }
    for (int i = t; i < 32 * 32; i += 256) {
        int r = i >> 5, c4 = i & 31;
        float4 v = make_float4(0.f, 0.f, 0.f, 0.f);
        if (row0 + r < NN) v = *(const float4*)&g_C1[(size_t)(row0 + r) * 512 + c4 * 4];
        *(float4*)&qs[r][c4 * 4] = v;
    }
    for (int i = t; i < 32 * 64; i += 256) {
        int r = i >> 6, dp = (i & 63) * 2;
        if (row0 + r < NN) {
            float2 v = *(const float2*)&g_C1[(size_t)(row0 + r) * 512 + 384 + dp];
            v.x = v.x > 0.f ? v.x : expm1f(v.x);
            v.y = v.y > 0.f ? v.y : expm1f(v.y);
            __nv_bfloat16 hx = __float2bfloat16(v.x), hy = __float2bfloat16(v.y);
            size_t idx = (size_t)(row0 + r) * 256 + dp;
            *(__nv_bfloat162*)&g_h_hi[idx] = __nv_bfloat162(hx, hy);
            *(__nv_bfloat162*)&g_h_lo[idx] =
                __nv_bfloat162(__float2bfloat16(v.x - __bfloat162float(hx)),
                               __float2bfloat16(v.y - __bfloat162float(hy)));
        }
    }
    __syncthreads();
    int h = t >> 5, r = t & 31;
    if (row0 + r >= NN) return;
    ull q2[8];
    float diag = 0.f;
#pragma unroll
    for (int d4 = 0; d4 < 4; d4++) {
        float4 v = *(const float4*)&qs[r][h * 16 + d4 * 4];
        float a = v.x * 0.5f, b = v.y * 0.5f, c = v.z * 0.5f, d = v.w * 0.5f;
        q2[d4 * 2] = pack2(a, b);
        q2[d4 * 2 + 1] = pack2(c, d);
        diag += a * a + b * b + c * c + d * d;
    }
    diag *= 0.5f;
    float dash[NBF];
    float qmax = -3e38f;
#pragma unroll
    for (int m = 0; m < NBF; m++) {
        ull s2 = 0;
#pragma unroll
        for (int d4 = 0; d4 < 4; d4++) {
            float4 p = *(const float4*)&proj_s[m * 16 + d4 * 4];
            s2 = fma2(q2[d4 * 2], pack2(p.x, p.y), s2);
            s2 = fma2(q2[d4 * 2 + 1], pack2(p.z, p.w), s2);
        }
        float sx, sy;
        unpack2(s2, sx, sy);
        dash[m] = sx + sy;
        qmax = fmaxf(qmax, dash[m]);
    }
    float den = 0.f;
    ull outv2[8];
#pragma unroll
    for (int d2 = 0; d2 < 8; d2++) outv2[d2] = 0;
    const float ratio = rsqrtf((float)NBF);
#pragma unroll
    for (int m = 0; m < NBF; m++) {
        float qp = ratio * (fexp(dash[m] - diag - qmax) + EPSV);
        den += qp * kcum_s[h * NBF + m];
        ull qp2 = pack2(qp, qp);
#pragma unroll
        for (int d4 = 0; d4 < 4; d4++) {
            float4 cv = *(const float4*)&ctxr[h][m * 16 + d4 * 4];
            outv2[d4 * 2] = fma2(qp2, pack2(cv.x, cv.y), outv2[d4 * 2]);
            outv2[d4 * 2 + 1] = fma2(qp2, pack2(cv.z, cv.w), outv2[d4 * 2 + 1]);
        }
    }
    float dinv = 1.f / den;
    size_t hbase = (size_t)(row0 + r) * 256 + HIDDIM + h * HDIM;
#pragma unroll
    for (int d2 = 0; d2 < 8; d2++) {
        float x, y;
        unpack2(outv2[d2], x, y);
        x *= dinv; y *= dinv;
        x = x > 0.f ? x : expm1f(x);
        y = y > 0.f ? y : expm1f(y);
        __nv_bfloat16 hx = __float2bfloat16(x), hy = __float2bfloat16(y);
        *(__nv_bfloat162*)&g_h_hi[hbase + d2 * 2] = __nv_bfloat162(hx, hy);
        *(__nv_bfloat162*)&g_h_lo[hbase + d2 * 2] =
            __nv_bfloat162(__float2bfloat16(x - __bfloat162float(hx)),
                           __float2bfloat16(y - __bfloat162float(hy)));
    }
}

// ---------------- APPNP graph prep ----------------
__global__ void deg_kernel(const int* __restrict__ col) {
    int e = blockIdx.x * blockDim.x + threadIdx.x;
    if (e < NEDGE) atomicAdd(&g_cnt[col[e]], 1);
}

__global__ __launch_bounds__(1024) void scan_kernel() {
    __shared__ int wsum[32];
    __shared__ int carry_s;
    int t = threadIdx.x;
    int lane = t & 31, wid = t >> 5;
    if (t == 0) carry_s = 0;
    __syncthreads();
    for (int base = 0; base < NN; base += 1024) {
        int i = base + t;
        int v = (i < NN) ? g_cnt[i] : 0;
        int x = v;
#pragma unroll
        for (int o = 1; o < 32; o <<= 1) {
            int y = __shfl_up_sync(0xffffffffu, x, o);
            if (lane >= o) x += y;
        }
        if (lane == 31) wsum[wid] = x;
        __syncthreads();
        if (wid == 0) {
            int s = wsum[lane];
#pragma unroll
            for (int o = 1; o < 32; o <<= 1) {
                int y = __shfl_up_sync(0xffffffffu, s, o);
                if (lane >= o) s += y;
            }
            wsum[lane] = s;
        }
        __syncthreads();
        int incl = x + (wid > 0 ? wsum[wid - 1] : 0);
        int carry = carry_s;
        if (i < NN) {
            int off = carry + incl - v;
            g_off[i] = off;
            g_cursor[i] = off;
            g_dis[i] = rsqrtf((float)(v + 1));
        }
        __syncthreads();
        if (t == 1023) carry_s = carry + incl;
        __syncthreads();
    }
    if (t == 0) g_off[NN] = carry_s;
}

__global__ void fill_kernel(const int* __restrict__ row, const int* __restrict__ col) {
    int e = blockIdx.x * blockDim.x + threadIdx.x;
    if (e >= NEDGE) return;
    int r = row[e], cl = col[e];
    int pos = atomicAdd(&g_cursor[cl], 1);
    g_csr[pos] = make_int2(r, __float_as_int(g_dis[r] * g_dis[cl]));
}

// ---------------- APPNP hop: 2 nodes per warp (16 lanes each), 16-deep MLP --------
template <bool LAST>
__global__ __launch_bounds__(256) void hop_kernel(int stage, float* __restrict__ out,
                                                  int out_size) {
    int gwarp = blockIdx.x * 8 + (threadIdx.x >> 5);
    int lane = threadIdx.x & 31;
    int sub = lane >> 4, li = lane & 15;
    int node = gwarp * 2 + sub;          // NN even; all nodes covered
    bool valid = node < NN;
    const __half* src = (stage == 0) ? g_x0h : ((stage & 1) ? g_ha : g_hb);
    __half* dst = (stage & 1) ? g_hb : g_ha;
    int s = 0, e = 0;
    if (valid) { s = g_off[node]; e = g_off[node + 1]; }
    int deg = e - s;
    int mdeg = deg;
#pragma unroll
    for (int o = 16; o > 0; o >>= 1) mdeg = max(mdeg, __shfl_xor_sync(0xffffffffu, mdeg, o));
    float di = valid ? g_dis[node] : 0.f;
    float4 x0v = make_float4(0.f, 0.f, 0.f, 0.f);
    float a0, a1, a2, a3;
    {
        uint2 sv = make_uint2(0u, 0u);
        if (valid) {
            x0v = *(const float4*)&g_x0[(size_t)node * 64 + li * 4];
            sv = *(const uint2*)&src[(size_t)node * 64 + li * 4];
        }
        float2 p0 = __half22float2(*(__half2*)&sv.x);
        float2 p1 = __half22float2(*(__half2*)&sv.y);
        float dd = di * di;
        a0 = dd * p0.x; a1 = dd * p0.y; a2 = dd * p1.x; a3 = dd * p1.y;
    }
    for (int jj = 0; jj < mdeg; jj += 8) {
        int2 ce[8];
#pragma unroll
        for (int u = 0; u < 8; u++)
            ce[u] = (jj + u < deg) ? g_csr[s + jj + u] : make_int2(0, 0);
#pragma unroll
        for (int u = 0; u < 8; u++) {
            if (jj + u < deg) {
                float wt = __int_as_float(ce[u].y);
                uint2 v = *(const uint2*)&src[(size_t)ce[u].x * 64 + li * 4];
                float2 p0 = __half22float2(*(__half2*)&v.x);
                float2 p1 = __half22float2(*(__half2*)&v.y);
                a0 += wt * p0.x; a1 += wt * p0.y; a2 += wt * p1.x; a3 += wt * p1.y;
            }
        }
    }
    float r0 = (1.f - ALPHAV) * a0 + ALPHAV * x0v.x;
    float r1 = (1.f - ALPHAV) * a1 + ALPHAV * x0v.y;
    float r2 = (1.f - ALPHAV) * a2 + ALPHAV * x0v.z;
    float r3 = (1.f - ALPHAV) * a3 + ALPHAV * x0v.w;
    if (!valid) return;
    if (!LAST) {
        uint2 o2;
        *(__half2*)&o2.x = __floats2half2_rn(r0, r1);
        *(__half2*)&o2.y = __floats2half2_rn(r2, r3);
        *(uint2*)&dst[(size_t)node * 64 + li * 4] = o2;
    } else {
        float mx = fmaxf(fmaxf(r0, r1), fmaxf(r2, r3));
#pragma unroll
        for (int o = 8; o > 0; o >>= 1) mx = fmaxf(mx, __shfl_xor_sync(0xffffffffu, mx, o));
        float ss = __expf(r0 - mx) + __expf(r1 - mx) + __expf(r2 - mx) + __expf(r3 - mx);
#pragma unroll
        for (int o = 8; o > 0; o >>= 1) ss += __shfl_xor_sync(0xffffffffu, ss, o);
        float lse = mx + logf(ss);
        int i0 = node * 64 + li * 4;
        if (i0 + 3 < out_size)
            *(float4*)&out[i0] = make_float4(r0 - lse, r1 - lse, r2 - lse, r3 - lse);
        int j0 = NN * 64 + i0;
        if (j0 + 3 < out_size)
            *(float4*)&out[j0] = make_float4(r0, r1, r2, r3);
    }
}

// ---------------- launch ----------------
extern "C" void kernel_launch(void* const* d_in, const int* in_sizes, int n_in,
                              void* d_out, int out_size) {
    if (n_in < 13) return;
    const float* data = (const float*)d_in[0];
    const int* ei = (const int*)d_in[1];
    const float* l1w = (const float*)d_in[2];
    const float* l1b = (const float*)d_in[3];
    const float* l2w = (const float*)d_in[4];
    const float* l2b = (const float*)d_in[5];
    const float* qw = (const float*)d_in[6];
    const float* qb = (const float*)d_in[7];
    const float* kw = (const float*)d_in[8];
    const float* kb = (const float*)d_in[9];
    const float* vw = (const float*)d_in[10];
    const float* vb = (const float*)d_in[11];
    const float* proj = (const float*)d_in[12];
    const int* row = ei;
    const int* col = ei + NEDGE;

    cudaFuncSetAttribute(hmma_gemm_kernel, cudaFuncAttributeMaxDynamicSharedMemorySize, HG_SMEM);
    cudaFuncSetAttribute(gemm2_kernel, cudaFuncAttributeMaxDynamicSharedMemorySize, G2_SMEM);

    // side stream for the independent graph-prep chain (fork/join inside capture)
    cudaStream_t s2;
    cudaStreamCreate(&s2);
    cudaEvent_t evA, evB;
    cudaEventCreateWithFlags(&evA, cudaEventDisableTiming);
    cudaEventCreateWithFlags(&evB, cudaEventDisableTiming);

    prep_kernel<<<1024, 256>>>(data, qw, kw, vw, l1w, qb, kb, vb, l1b, l2w);
    cudaEventRecord(evA, 0);

    // branch: graph prep (needs only g_cnt init from prep + edge_index)
    cudaStreamWaitEvent(s2, evA, 0);
    deg_kernel<<<(NEDGE + 255) / 256, 256, 0, s2>>>(col);
    scan_kernel<<<1, 1024, 0, s2>>>();
    fill_kernel<<<(NEDGE + 255) / 256, 256, 0, s2>>>(row, col);
    cudaEventRecord(evB, s2);

    // main: GEMM + performer pipeline
    dim3 g1((NN + 127) / 128, 4);
    hmma_gemm_kernel<<<g1, 256, HG_SMEM>>>();
    kmax_kernel<<<NTILES, 256>>>(proj);
    kp_acc_kernel<<<KPB, 352>>>(proj);
    attn_kernel<<<NTILES, 256>>>(proj);
    gemm2_kernel<<<(NN + 127) / 128, 256, G2_SMEM>>>(l2b);

    // join graph-prep branch before hops
    cudaStreamWaitEvent(0, evB, 0);

    int hop_grid = (NN + 15) / 16;
    for (int k = 0; k < 9; k++)
        hop_kernel<false><<<hop_grid, 256>>>(k, nullptr, 0);
    hop_kernel<true><<<hop_grid, 256>>>(9, (float*)d_out, out_size);

    // destroy only when not capturing (destroying a joined-but-capturing stream is risky)
    cudaStreamCaptureStatus st = cudaStreamCaptureStatusNone;
    cudaStreamIsCapturing(s2, &st);
    if (st == cudaStreamCaptureStatusNone) {
        cudaEventDestroy(evA);
        cudaEventDestroy(evB);
        cudaStreamDestroy(s2);
    }
}